// round 8
// baseline (speedup 1.0000x reference)
#include <cuda_runtime.h>
#include <cuda_bf16.h>
#include <math.h>
#include <cstdint>

// ---------------- problem constants ----------------
#define BB 4
#define CC 3
#define HH 32
#define WW 32
#define NIMG 32
#define PP (NIMG*HH*WW)      // 32768 dataset patches
#define QQ (BB*HH*WW)        // 4096 queries
#define KD 27                // raw feature dim
// split K': [qh*kh (27)] [qh*kl (27)] [ql*kh (27)] pad -> 96 = 6 chunks of k16
#define KCH 6

#define PSPLIT 9             // 32 qtiles * 9 = 288 blocks ~= 148*2 (one wave at occ 2)
#define NQT 32               // q tiles of 128 rows
#define NPG (PP/8)           // 4096 patch groups of 8

// ---------------- device scratch (no allocation allowed) -------------------
// K fragments: [pg][chunkpair 0..2][lane] uint4 = (b0_even,b1_even,b0_odd,b1_odd)
__device__ uint4  g_kfrag[NPG * 3 * 32];          // 6 MB
// Q fragments: [tile(16 rows)][chunk 0..5][lane] uint4 = (a0,a1,a2,a3)
__device__ uint4  g_qfrag[(QQ/16) * KCH * 32];    // 768 KB
__device__ float4 g_meta[PP];                     // c0,c1,c2,bias(log2 domain)
__device__ float  g_partial[QQ * PSPLIT * 8];     // m,sw,c0,c1,c2 per (q,split)

// ---------------- helpers ----------------------------------------------
__device__ __forceinline__ float ex2f(float x) {
    float r; asm("ex2.approx.f32 %0,%1;" : "=f"(r) : "f"(x)); return r;
}
__device__ __forceinline__ void split_bf16(float v, unsigned short& h, unsigned short& l) {
    __nv_bfloat16 hb = __float2bfloat16_rn(v);
    float rem = v - __bfloat162float(hb);
    __nv_bfloat16 lb = __float2bfloat16_rn(rem);
    h = __bfloat16_as_ushort(hb);
    l = __bfloat16_as_ushort(lb);
}
#define MMA_BF16(d0,d1,d2,d3,a0,a1,a2,a3,b0,b1) \
    asm volatile("mma.sync.aligned.m16n8k16.row.col.f32.bf16.bf16.f32 " \
                 "{%0,%1,%2,%3}, {%4,%5,%6,%7}, {%8,%9}, {%0,%1,%2,%3};" \
                 : "+f"(d0), "+f"(d1), "+f"(d2), "+f"(d3) \
                 : "r"(a0), "r"(a1), "r"(a2), "r"(a3), "r"(b0), "r"(b1))

// ---------------------------------------------------------------------------
// Prep: build fragment-major Q/K split-bf16 data + per-patch meta.
// log2-domain: q scaled by 2*mu/(2 sigma^2)*log2(e); bias = -mu^2/(2s^2)*log2e*||k||^2
// ---------------------------------------------------------------------------
__global__ void prep_kernel(const float* __restrict__ x,
                            const float* __restrict__ images,
                            const float* __restrict__ mu_sched,
                            const float* __restrict__ sigma_sched,
                            const int* __restrict__ tptr)
{
    const int t = *tptr;
    const float mu = mu_sched[t];
    const float sg = sigma_sched[t];
    const float LOG2E = 1.4426950408889634f;
    const float inv2s2 = 1.0f / (2.0f * sg * sg);
    const float a  = 2.0f * mu * inv2s2 * LOG2E;
    const float nb = -mu * mu * inv2s2 * LOG2E;

    int gid = blockIdx.x * blockDim.x + threadIdx.x;

    float f[KD];
    unsigned short hb[KD], lb[KD];
    unsigned short v[96];

    if (gid < PP) {
        // ---- dataset patch (zero pad) ----
        int p = gid;
        int n = p >> 10, i = (p >> 5) & 31, j = p & 31;
        float pn = 0.0f;
        #pragma unroll
        for (int c = 0; c < CC; c++)
            #pragma unroll
            for (int di = 0; di < 3; di++)
                #pragma unroll
                for (int dj = 0; dj < 3; dj++) {
                    int ii = i + di - 1, jj = j + dj - 1;
                    float vv = 0.0f;
                    if (ii >= 0 && ii < HH && jj >= 0 && jj < WW)
                        vv = images[(((n*CC + c) << 5) + ii) * WW + jj];
                    f[c*9 + di*3 + dj] = vv;
                    pn += vv * vv;
                }
        #pragma unroll
        for (int k = 0; k < KD; k++) split_bf16(f[k], hb[k], lb[k]);
        // B row: [kh(27)][kl(27)][kh(27)][pad]
        #pragma unroll
        for (int k = 0; k < 96; k++)
            v[k] = (k < 27) ? hb[k] : (k < 54) ? lb[k-27] : (k < 81) ? hb[k-54] : 0;

        int pg = p >> 3, nn = p & 7;
        #pragma unroll
        for (int cp = 0; cp < 3; cp++) {
            int c0 = 2*cp*16, c1 = (2*cp+1)*16;
            #pragma unroll
            for (int tt = 0; tt < 4; tt++) {
                uint4 val;
                val.x = (unsigned)v[c0 + 2*tt]     | ((unsigned)v[c0 + 2*tt + 1] << 16);
                val.y = (unsigned)v[c0 + 2*tt + 8] | ((unsigned)v[c0 + 2*tt + 9] << 16);
                val.z = (unsigned)v[c1 + 2*tt]     | ((unsigned)v[c1 + 2*tt + 1] << 16);
                val.w = (unsigned)v[c1 + 2*tt + 8] | ((unsigned)v[c1 + 2*tt + 9] << 16);
                g_kfrag[((pg*3 + cp) << 5) + nn*4 + tt] = val;
            }
        }
        g_meta[p] = make_float4(f[4], f[13], f[22], nb * pn);
    } else if (gid < PP + QQ) {
        // ---- query (wrap pad, scaled) ----
        int q = gid - PP;
        int b = q >> 10, h = (q >> 5) & 31, w0 = q & 31;
        #pragma unroll
        for (int c = 0; c < CC; c++)
            #pragma unroll
            for (int di = 0; di < 3; di++)
                #pragma unroll
                for (int dj = 0; dj < 3; dj++) {
                    int ii = (h + di - 1) & 31, jj = (w0 + dj - 1) & 31;
                    f[c*9 + di*3 + dj] = a * x[(((b*CC + c) << 5) + ii) * WW + jj];
                }
        #pragma unroll
        for (int k = 0; k < KD; k++) split_bf16(f[k], hb[k], lb[k]);
        // A row: [qh(27)][qh(27)][ql(27)][pad]
        #pragma unroll
        for (int k = 0; k < 96; k++)
            v[k] = (k < 27) ? hb[k] : (k < 54) ? hb[k-27] : (k < 81) ? lb[k-54] : 0;

        int tile = q >> 4, r = q & 15, rg = r & 7, rh = r >> 3;
        unsigned* qf = (unsigned*)g_qfrag;
        #pragma unroll
        for (int c = 0; c < KCH; c++) {
            #pragma unroll
            for (int tt = 0; tt < 4; tt++) {
                unsigned lo = (unsigned)v[c*16 + 2*tt]     | ((unsigned)v[c*16 + 2*tt + 1] << 16);
                unsigned hi = (unsigned)v[c*16 + 2*tt + 8] | ((unsigned)v[c*16 + 2*tt + 9] << 16);
                unsigned base4 = (((tile*KCH + c) << 5) + rg*4 + tt) << 2;
                qf[base4 + rh]     = lo;   // a0 (row g) or a1 (row g+8)
                qf[base4 + 2 + rh] = hi;   // a2 / a3
            }
        }
    }
}

// ---------------------------------------------------------------------------
// Main: mma.sync flash-attention. 288 blocks (32 qtiles x 9 psplits), 256 thr.
// Each warp: 16 q-rows, sweeps its split's patch groups (8 patches per step).
// ---------------------------------------------------------------------------
__device__ __forceinline__ void merge_state(float& m, float& sw, float& a,
                                            float& b, float& c, int off)
{
    float mo = __shfl_down_sync(0xffffffffu, m,  off, 4);
    float so = __shfl_down_sync(0xffffffffu, sw, off, 4);
    float ao = __shfl_down_sync(0xffffffffu, a,  off, 4);
    float bo = __shfl_down_sync(0xffffffffu, b,  off, 4);
    float co = __shfl_down_sync(0xffffffffu, c,  off, 4);
    float M  = fmaxf(m, mo);
    float f0 = ex2f(m - M), f1 = ex2f(mo - M);
    sw = sw*f0 + so*f1;
    a  = a*f0  + ao*f1;
    b  = b*f0  + bo*f1;
    c  = c*f0  + co*f1;
    m  = M;
}

__global__ void __launch_bounds__(256, 2)
score_main_kernel()
{
    const int bid  = blockIdx.x;
    const int qt   = bid & 31;
    const int sp   = bid >> 5;          // 0..8
    const int w    = threadIdx.x >> 5;
    const int lane = threadIdx.x & 31;
    const int g    = lane >> 2;         // q-row group (rows g, g+8)
    const int t    = lane & 3;          // column pair (cols 2t, 2t+1)

    // A fragments for this warp's 16 q-rows
    const int tile = qt * 8 + w;
    uint4 af[KCH];
    #pragma unroll
    for (int c = 0; c < KCH; c++)
        af[c] = g_qfrag[((tile*KCH + c) << 5) + lane];

    float m0 = -1e30f, sw0 = 0.f, c00 = 0.f, c01 = 0.f, c02 = 0.f;
    float m1 = -1e30f, sw1 = 0.f, c10 = 0.f, c11 = 0.f, c12 = 0.f;

    const int G0 = (NPG * sp) / PSPLIT;
    const int G1 = (NPG * (sp + 1)) / PSPLIT;

    #pragma unroll 2
    for (int pg = G0; pg < G1; pg++) {
        uint4 b01 = g_kfrag[((pg*3 + 0) << 5) + lane];
        uint4 b23 = g_kfrag[((pg*3 + 1) << 5) + lane];
        uint4 b45 = g_kfrag[((pg*3 + 2) << 5) + lane];
        float4 me0 = g_meta[(pg << 3) + 2*t];
        float4 me1 = g_meta[(pg << 3) + 2*t + 1];

        // D init = per-column bias
        float d0 = me0.w, d1 = me1.w, d2 = me0.w, d3 = me1.w;
        MMA_BF16(d0,d1,d2,d3, af[0].x,af[0].y,af[0].z,af[0].w, b01.x,b01.y);
        MMA_BF16(d0,d1,d2,d3, af[1].x,af[1].y,af[1].z,af[1].w, b01.z,b01.w);
        MMA_BF16(d0,d1,d2,d3, af[2].x,af[2].y,af[2].z,af[2].w, b23.x,b23.y);
        MMA_BF16(d0,d1,d2,d3, af[3].x,af[3].y,af[3].z,af[3].w, b23.z,b23.w);
        MMA_BF16(d0,d1,d2,d3, af[4].x,af[4].y,af[4].z,af[4].w, b45.x,b45.y);
        MMA_BF16(d0,d1,d2,d3, af[5].x,af[5].y,af[5].z,af[5].w, b45.z,b45.w);

        // row g: logits d0 (col 2t), d1 (col 2t+1)
        {
            float mx = fmaxf(d0, d1);
            if (mx > m0) {
                float cr = ex2f(m0 - mx);
                sw0 *= cr; c00 *= cr; c01 *= cr; c02 *= cr;
                m0 = mx;
            }
            float w0 = ex2f(d0 - m0), w1 = ex2f(d1 - m0);
            sw0 += w0 + w1;
            c00 += w0*me0.x + w1*me1.x;
            c01 += w0*me0.y + w1*me1.y;
            c02 += w0*me0.z + w1*me1.z;
        }
        // row g+8: logits d2, d3
        {
            float mx = fmaxf(d2, d3);
            if (mx > m1) {
                float cr = ex2f(m1 - mx);
                sw1 *= cr; c10 *= cr; c11 *= cr; c12 *= cr;
                m1 = mx;
            }
            float w0 = ex2f(d2 - m1), w1 = ex2f(d3 - m1);
            sw1 += w0 + w1;
            c10 += w0*me0.x + w1*me1.x;
            c11 += w0*me0.y + w1*me1.y;
            c12 += w0*me0.z + w1*me1.z;
        }
    }

    // reduce the 4 column-group lanes (t = 0..3) of each row
    #pragma unroll
    for (int off = 1; off <= 2; off <<= 1) {
        merge_state(m0, sw0, c00, c01, c02, off);
        merge_state(m1, sw1, c10, c11, c12, off);
    }

    if (t == 0) {
        int qrow0 = qt*128 + w*16 + g;
        float* o0 = g_partial + ((size_t)qrow0 * PSPLIT + sp) * 8;
        o0[0] = m0; o0[1] = sw0; o0[2] = c00; o0[3] = c01; o0[4] = c02;
        float* o1 = g_partial + ((size_t)(qrow0 + 8) * PSPLIT + sp) * 8;
        o1[0] = m1; o1[1] = sw1; o1[2] = c10; o1[3] = c11; o1[4] = c12;
    }
}

// ---------------------------------------------------------------------------
// Finalize: merge PSPLIT partials per query (log2 domain), form output.
// ---------------------------------------------------------------------------
__global__ void finalize_kernel(const float* __restrict__ x,
                                const float* __restrict__ mu_sched,
                                const float* __restrict__ sigma_sched,
                                const int* __restrict__ tptr,
                                float* __restrict__ out)
{
    int q = blockIdx.x * blockDim.x + threadIdx.x;
    if (q >= QQ) return;

    const int t = *tptr;
    const float mu = mu_sched[t];
    const float sg = sigma_sched[t];
    const float is2 = 1.0f / (sg * sg);

    const float* pr = g_partial + (size_t)q * PSPLIT * 8;

    float M = -1e30f;
    #pragma unroll
    for (int i = 0; i < PSPLIT; i++) M = fmaxf(M, pr[i*8]);

    float S = 0.f, c0 = 0.f, c1 = 0.f, c2 = 0.f;
    #pragma unroll
    for (int i = 0; i < PSPLIT; i++) {
        float cr = ex2f(pr[i*8] - M);
        S  += pr[i*8 + 1] * cr;
        c0 += pr[i*8 + 2] * cr;
        c1 += pr[i*8 + 3] * cr;
        c2 += pr[i*8 + 4] * cr;
    }
    float inv = 1.0f / S;

    int b = q >> 10;
    int pix = q & 1023;

    out[((b*CC + 0) << 10) + pix] = -(x[((b*CC + 0) << 10) + pix] - mu * c0 * inv) * is2;
    out[((b*CC + 1) << 10) + pix] = -(x[((b*CC + 1) << 10) + pix] - mu * c1 * inv) * is2;
    out[((b*CC + 2) << 10) + pix] = -(x[((b*CC + 2) << 10) + pix] - mu * c2 * inv) * is2;
}

// ---------------------------------------------------------------------------
extern "C" void kernel_launch(void* const* d_in, const int* in_sizes, int n_in,
                              void* d_out, int out_size)
{
    const float* x      = (const float*)d_in[0];
    const float* images = (const float*)d_in[1];
    const float* mu_s   = (const float*)d_in[2];
    const float* sg_s   = (const float*)d_in[3];
    const int*   tptr   = (const int*)d_in[4];
    float* out = (float*)d_out;

    prep_kernel<<<(PP + QQ + 255) / 256, 256>>>(x, images, mu_s, sg_s, tptr);
    score_main_kernel<<<NQT * PSPLIT, 256>>>();
    finalize_kernel<<<(QQ + 255) / 256, 256>>>(x, mu_s, sg_s, tptr, out);
}

// round 9
// speedup vs baseline: 1.1402x; 1.1402x over previous
#include <cuda_runtime.h>
#include <cuda_bf16.h>
#include <math.h>
#include <cstdint>

// ---------------- problem constants ----------------
#define BB 4
#define CC 3
#define HH 32
#define WW 32
#define NIMG 32
#define PP (NIMG*HH*WW)      // 32768 dataset patches
#define QQ (BB*HH*WW)        // 4096 queries
#define KD 27                // raw feature dim
// split K': [qh*kh (27)] [qh*kl (27)] [ql*kh (27)] pad -> 96 = 6 chunks of k16
#define KCH 6

#define NQB 16               // q blocks of 256 rows
#define PSPLIT 18            // 16*18 = 288 blocks = one wave at occ 2
#define NPG (PP/8)           // 4096 patch groups of 8
#define STAGE 8              // patch groups per smem stage

// ---------------- device scratch (no allocation allowed) -------------------
// K fragments: [pg][chunkpair 0..2][lane] uint4  (96 uint4 per pg, contiguous)
__device__ uint4  g_kfrag[NPG * 3 * 32];          // 6 MB
// Q fragments: [tile(16 rows)][chunk 0..5][lane] uint4 = (a0,a1,a2,a3)
__device__ uint4  g_qfrag[(QQ/16) * KCH * 32];    // 768 KB
__device__ float4 g_meta[PP];                     // c0,c1,c2,bias(log2 domain)
__device__ float  g_partial[QQ * PSPLIT * 8];     // m,sw,c0,c1,c2 per (q,split)

// ---------------- helpers ----------------------------------------------
__device__ __forceinline__ float ex2f(float x) {
    float r; asm("ex2.approx.f32 %0,%1;" : "=f"(r) : "f"(x)); return r;
}
__device__ __forceinline__ uint32_t smem_u32(const void* p) {
    uint32_t a;
    asm("{ .reg .u64 t; cvta.to.shared.u64 t, %1; cvt.u32.u64 %0, t; }"
        : "=r"(a) : "l"(p));
    return a;
}
__device__ __forceinline__ void cp_async16(uint32_t dst, const void* src) {
    asm volatile("cp.async.cg.shared.global [%0], [%1], 16;"
                 :: "r"(dst), "l"(src));
}
#define CP_COMMIT() asm volatile("cp.async.commit_group;" ::: "memory")
#define CP_WAIT1()  asm volatile("cp.async.wait_group 1;" ::: "memory")

__device__ __forceinline__ void split_bf16(float v, unsigned short& h, unsigned short& l) {
    __nv_bfloat16 hb = __float2bfloat16_rn(v);
    float rem = v - __bfloat162float(hb);
    __nv_bfloat16 lb = __float2bfloat16_rn(rem);
    h = __bfloat16_as_ushort(hb);
    l = __bfloat16_as_ushort(lb);
}
#define MMA_BF16(d0,d1,d2,d3,a0,a1,a2,a3,b0,b1) \
    asm volatile("mma.sync.aligned.m16n8k16.row.col.f32.bf16.bf16.f32 " \
                 "{%0,%1,%2,%3}, {%4,%5,%6,%7}, {%8,%9}, {%0,%1,%2,%3};" \
                 : "+f"(d0), "+f"(d1), "+f"(d2), "+f"(d3) \
                 : "r"(a0), "r"(a1), "r"(a2), "r"(a3), "r"(b0), "r"(b1))

// ---------------------------------------------------------------------------
// Prep: build fragment-major Q/K split-bf16 data + per-patch meta.
// ---------------------------------------------------------------------------
__global__ void prep_kernel(const float* __restrict__ x,
                            const float* __restrict__ images,
                            const float* __restrict__ mu_sched,
                            const float* __restrict__ sigma_sched,
                            const int* __restrict__ tptr)
{
    const int t = *tptr;
    const float mu = mu_sched[t];
    const float sg = sigma_sched[t];
    const float LOG2E = 1.4426950408889634f;
    const float inv2s2 = 1.0f / (2.0f * sg * sg);
    const float a  = 2.0f * mu * inv2s2 * LOG2E;
    const float nb = -mu * mu * inv2s2 * LOG2E;

    int gid = blockIdx.x * blockDim.x + threadIdx.x;

    float f[KD];
    unsigned short hb[KD], lb[KD];
    unsigned short v[96];

    if (gid < PP) {
        int p = gid;
        int n = p >> 10, i = (p >> 5) & 31, j = p & 31;
        float pn = 0.0f;
        #pragma unroll
        for (int c = 0; c < CC; c++)
            #pragma unroll
            for (int di = 0; di < 3; di++)
                #pragma unroll
                for (int dj = 0; dj < 3; dj++) {
                    int ii = i + di - 1, jj = j + dj - 1;
                    float vv = 0.0f;
                    if (ii >= 0 && ii < HH && jj >= 0 && jj < WW)
                        vv = images[(((n*CC + c) << 5) + ii) * WW + jj];
                    f[c*9 + di*3 + dj] = vv;
                    pn += vv * vv;
                }
        #pragma unroll
        for (int k = 0; k < KD; k++) split_bf16(f[k], hb[k], lb[k]);
        #pragma unroll
        for (int k = 0; k < 96; k++)
            v[k] = (k < 27) ? hb[k] : (k < 54) ? lb[k-27] : (k < 81) ? hb[k-54] : 0;

        int pg = p >> 3, nn = p & 7;
        #pragma unroll
        for (int cp = 0; cp < 3; cp++) {
            int c0 = 2*cp*16, c1 = (2*cp+1)*16;
            #pragma unroll
            for (int tt = 0; tt < 4; tt++) {
                uint4 val;
                val.x = (unsigned)v[c0 + 2*tt]     | ((unsigned)v[c0 + 2*tt + 1] << 16);
                val.y = (unsigned)v[c0 + 2*tt + 8] | ((unsigned)v[c0 + 2*tt + 9] << 16);
                val.z = (unsigned)v[c1 + 2*tt]     | ((unsigned)v[c1 + 2*tt + 1] << 16);
                val.w = (unsigned)v[c1 + 2*tt + 8] | ((unsigned)v[c1 + 2*tt + 9] << 16);
                g_kfrag[((pg*3 + cp) << 5) + nn*4 + tt] = val;
            }
        }
        g_meta[p] = make_float4(f[4], f[13], f[22], nb * pn);
    } else if (gid < PP + QQ) {
        int q = gid - PP;
        int b = q >> 10, h = (q >> 5) & 31, w0 = q & 31;
        #pragma unroll
        for (int c = 0; c < CC; c++)
            #pragma unroll
            for (int di = 0; di < 3; di++)
                #pragma unroll
                for (int dj = 0; dj < 3; dj++) {
                    int ii = (h + di - 1) & 31, jj = (w0 + dj - 1) & 31;
                    f[c*9 + di*3 + dj] = a * x[(((b*CC + c) << 5) + ii) * WW + jj];
                }
        #pragma unroll
        for (int k = 0; k < KD; k++) split_bf16(f[k], hb[k], lb[k]);
        #pragma unroll
        for (int k = 0; k < 96; k++)
            v[k] = (k < 27) ? hb[k] : (k < 54) ? hb[k-27] : (k < 81) ? lb[k-54] : 0;

        int tile = q >> 4, r = q & 15, rg = r & 7, rh = r >> 3;
        unsigned* qf = (unsigned*)g_qfrag;
        #pragma unroll
        for (int c = 0; c < KCH; c++) {
            #pragma unroll
            for (int tt = 0; tt < 4; tt++) {
                unsigned lo = (unsigned)v[c*16 + 2*tt]     | ((unsigned)v[c*16 + 2*tt + 1] << 16);
                unsigned hi = (unsigned)v[c*16 + 2*tt + 8] | ((unsigned)v[c*16 + 2*tt + 9] << 16);
                unsigned base4 = (((tile*KCH + c) << 5) + rg*4 + tt) << 2;
                qf[base4 + rh]     = lo;
                qf[base4 + 2 + rh] = hi;
            }
        }
    }
}

// ---------------------------------------------------------------------------
// Main: smem-staged mma.sync flash-attention.
// Grid 16 q-blocks (256 rows) x 18 p-splits; 256 thr; warp = 32 q-rows (2 tiles).
// ---------------------------------------------------------------------------
__device__ __forceinline__ void merge_state(float& m, float& sw, float& a,
                                            float& b, float& c, int off)
{
    float mo = __shfl_down_sync(0xffffffffu, m,  off, 4);
    float so = __shfl_down_sync(0xffffffffu, sw, off, 4);
    float ao = __shfl_down_sync(0xffffffffu, a,  off, 4);
    float bo = __shfl_down_sync(0xffffffffu, b,  off, 4);
    float co = __shfl_down_sync(0xffffffffu, c,  off, 4);
    float M  = fmaxf(m, mo);
    float f0 = ex2f(m - M), f1 = ex2f(mo - M);
    sw = sw*f0 + so*f1;
    a  = a*f0  + ao*f1;
    b  = b*f0  + bo*f1;
    c  = c*f0  + co*f1;
    m  = M;
}

__global__ void __launch_bounds__(256, 2)
score_main_kernel()
{
    __shared__ __align__(16) uint4  kbuf[2][STAGE*96];   // 2 x 12 KB
    __shared__ __align__(16) float4 mbuf[2][STAGE*8];    // 2 x 1 KB

    const int bid  = blockIdx.x;
    const int qb   = bid & 15;
    const int sp   = bid >> 4;          // 0..17
    const int tid  = threadIdx.x;
    const int w    = tid >> 5;
    const int lane = tid & 31;
    const int g    = lane >> 2;         // q-row group
    const int t    = lane & 3;          // column pair

    // A fragments: 2 row-sets of 16 q-rows each
    uint4 af[2][KCH];
    #pragma unroll
    for (int rs = 0; rs < 2; rs++) {
        int tile = qb*16 + w*2 + rs;
        #pragma unroll
        for (int c = 0; c < KCH; c++)
            af[rs][c] = g_qfrag[((tile*KCH + c) << 5) + lane];
    }

    float m_[2][2], sw_[2][2], ca_[2][2], cb_[2][2], cc_[2][2];
    #pragma unroll
    for (int rs = 0; rs < 2; rs++)
        #pragma unroll
        for (int rr = 0; rr < 2; rr++) {
            m_[rs][rr] = -1e30f; sw_[rs][rr] = 0.f;
            ca_[rs][rr] = 0.f; cb_[rs][rr] = 0.f; cc_[rs][rr] = 0.f;
        }

    const int G0 = (NPG * sp) / PSPLIT;
    const int G1 = (NPG * (sp + 1)) / PSPLIT;
    const int nstages = (G1 - G0 + STAGE - 1) / STAGE;

    const uint32_t kaddr0 = smem_u32(&kbuf[0][0]);
    const uint32_t kaddr1 = smem_u32(&kbuf[1][0]);
    const uint32_t maddr0 = smem_u32(&mbuf[0][0]);
    const uint32_t maddr1 = smem_u32(&mbuf[1][0]);

    // prefetch stage 0
    {
        int s = G0, cnt = (G1 - s < STAGE) ? (G1 - s) : STAGE;
        const uint4* ks = g_kfrag + (size_t)s * 96;
        for (int i = tid; i < cnt*96; i += 256)
            cp_async16(kaddr0 + i*16, ks + i);
        const float4* ms = g_meta + s*8;
        for (int i = tid; i < cnt*8; i += 256)
            cp_async16(maddr0 + i*16, ms + i);
    }
    CP_COMMIT();

    for (int st = 0; st < nstages; st++) {
        const int cur = st & 1;
        // prefetch next stage into other buffer
        {
            int s = G0 + (st + 1) * STAGE;
            if (s < G1) {
                int cnt = (G1 - s < STAGE) ? (G1 - s) : STAGE;
                uint32_t ka = cur ? kaddr0 : kaddr1;
                uint32_t ma = cur ? maddr0 : maddr1;
                const uint4* ks = g_kfrag + (size_t)s * 96;
                for (int i = tid; i < cnt*96; i += 256)
                    cp_async16(ka + i*16, ks + i);
                const float4* ms = g_meta + s*8;
                for (int i = tid; i < cnt*8; i += 256)
                    cp_async16(ma + i*16, ms + i);
            }
        }
        CP_COMMIT();
        CP_WAIT1();
        __syncthreads();

        const int s0  = G0 + st * STAGE;
        const int cnt = (G1 - s0 < STAGE) ? (G1 - s0) : STAGE;
        const uint4*  kb = kbuf[cur];
        const float4* mb = mbuf[cur];

        for (int jp = 0; jp < cnt; jp++) {
            uint4 b01 = kb[jp*96      + lane];
            uint4 b23 = kb[jp*96 + 32 + lane];
            uint4 b45 = kb[jp*96 + 64 + lane];
            float4 me0 = mb[jp*8 + 2*t];
            float4 me1 = mb[jp*8 + 2*t + 1];

            #pragma unroll
            for (int rs = 0; rs < 2; rs++) {
                float d0 = me0.w, d1 = me1.w, d2 = me0.w, d3 = me1.w;
                MMA_BF16(d0,d1,d2,d3, af[rs][0].x,af[rs][0].y,af[rs][0].z,af[rs][0].w, b01.x,b01.y);
                MMA_BF16(d0,d1,d2,d3, af[rs][1].x,af[rs][1].y,af[rs][1].z,af[rs][1].w, b01.z,b01.w);
                MMA_BF16(d0,d1,d2,d3, af[rs][2].x,af[rs][2].y,af[rs][2].z,af[rs][2].w, b23.x,b23.y);
                MMA_BF16(d0,d1,d2,d3, af[rs][3].x,af[rs][3].y,af[rs][3].z,af[rs][3].w, b23.z,b23.w);
                MMA_BF16(d0,d1,d2,d3, af[rs][4].x,af[rs][4].y,af[rs][4].z,af[rs][4].w, b45.x,b45.y);
                MMA_BF16(d0,d1,d2,d3, af[rs][5].x,af[rs][5].y,af[rs][5].z,af[rs][5].w, b45.z,b45.w);

                // row g
                {
                    float mx = fmaxf(d0, d1);
                    if (mx > m_[rs][0]) {
                        float cr = ex2f(m_[rs][0] - mx);
                        sw_[rs][0] *= cr; ca_[rs][0] *= cr; cb_[rs][0] *= cr; cc_[rs][0] *= cr;
                        m_[rs][0] = mx;
                    }
                    float w0 = ex2f(d0 - m_[rs][0]), w1 = ex2f(d1 - m_[rs][0]);
                    sw_[rs][0] += w0 + w1;
                    ca_[rs][0] += w0*me0.x + w1*me1.x;
                    cb_[rs][0] += w0*me0.y + w1*me1.y;
                    cc_[rs][0] += w0*me0.z + w1*me1.z;
                }
                // row g+8
                {
                    float mx = fmaxf(d2, d3);
                    if (mx > m_[rs][1]) {
                        float cr = ex2f(m_[rs][1] - mx);
                        sw_[rs][1] *= cr; ca_[rs][1] *= cr; cb_[rs][1] *= cr; cc_[rs][1] *= cr;
                        m_[rs][1] = mx;
                    }
                    float w0 = ex2f(d2 - m_[rs][1]), w1 = ex2f(d3 - m_[rs][1]);
                    sw_[rs][1] += w0 + w1;
                    ca_[rs][1] += w0*me0.x + w1*me1.x;
                    cb_[rs][1] += w0*me0.y + w1*me1.y;
                    cc_[rs][1] += w0*me0.z + w1*me1.z;
                }
            }
        }
        __syncthreads();
    }

    // reduce the 4 column-group lanes
    #pragma unroll
    for (int rs = 0; rs < 2; rs++)
        #pragma unroll
        for (int rr = 0; rr < 2; rr++)
            #pragma unroll
            for (int off = 1; off <= 2; off <<= 1)
                merge_state(m_[rs][rr], sw_[rs][rr], ca_[rs][rr], cb_[rs][rr], cc_[rs][rr], off);

    if (t == 0) {
        #pragma unroll
        for (int rs = 0; rs < 2; rs++) {
            int tile = qb*16 + w*2 + rs;
            #pragma unroll
            for (int rr = 0; rr < 2; rr++) {
                int qrow = tile*16 + g + rr*8;
                float* o = g_partial + ((size_t)qrow * PSPLIT + sp) * 8;
                o[0] = m_[rs][rr]; o[1] = sw_[rs][rr];
                o[2] = ca_[rs][rr]; o[3] = cb_[rs][rr]; o[4] = cc_[rs][rr];
            }
        }
    }
}

// ---------------------------------------------------------------------------
// Finalize: merge PSPLIT partials per query (log2 domain), form output.
// ---------------------------------------------------------------------------
__global__ void finalize_kernel(const float* __restrict__ x,
                                const float* __restrict__ mu_sched,
                                const float* __restrict__ sigma_sched,
                                const int* __restrict__ tptr,
                                float* __restrict__ out)
{
    int q = blockIdx.x * blockDim.x + threadIdx.x;
    if (q >= QQ) return;

    const int t = *tptr;
    const float mu = mu_sched[t];
    const float sg = sigma_sched[t];
    const float is2 = 1.0f / (sg * sg);

    const float* pr = g_partial + (size_t)q * PSPLIT * 8;

    float M = -1e30f;
    #pragma unroll
    for (int i = 0; i < PSPLIT; i++) M = fmaxf(M, pr[i*8]);

    float S = 0.f, c0 = 0.f, c1 = 0.f, c2 = 0.f;
    #pragma unroll
    for (int i = 0; i < PSPLIT; i++) {
        float cr = ex2f(pr[i*8] - M);
        S  += pr[i*8 + 1] * cr;
        c0 += pr[i*8 + 2] * cr;
        c1 += pr[i*8 + 3] * cr;
        c2 += pr[i*8 + 4] * cr;
    }
    float inv = 1.0f / S;

    int b = q >> 10;
    int pix = q & 1023;

    out[((b*CC + 0) << 10) + pix] = -(x[((b*CC + 0) << 10) + pix] - mu * c0 * inv) * is2;
    out[((b*CC + 1) << 10) + pix] = -(x[((b*CC + 1) << 10) + pix] - mu * c1 * inv) * is2;
    out[((b*CC + 2) << 10) + pix] = -(x[((b*CC + 2) << 10) + pix] - mu * c2 * inv) * is2;
}

// ---------------------------------------------------------------------------
extern "C" void kernel_launch(void* const* d_in, const int* in_sizes, int n_in,
                              void* d_out, int out_size)
{
    const float* x      = (const float*)d_in[0];
    const float* images = (const float*)d_in[1];
    const float* mu_s   = (const float*)d_in[2];
    const float* sg_s   = (const float*)d_in[3];
    const int*   tptr   = (const int*)d_in[4];
    float* out = (float*)d_out;

    prep_kernel<<<(PP + QQ + 255) / 256, 256>>>(x, images, mu_s, sg_s, tptr);
    score_main_kernel<<<NQB * PSPLIT, 256>>>();
    finalize_kernel<<<(QQ + 255) / 256, 256>>>(x, mu_s, sg_s, tptr, out);
}

// round 10
// speedup vs baseline: 1.4433x; 1.2659x over previous
#include <cuda_runtime.h>
#include <cuda_bf16.h>
#include <math.h>
#include <cstdint>

// ---------------- problem constants ----------------
#define BB 4
#define CC 3
#define HH 32
#define WW 32
#define NIMG 32
#define PP (NIMG*HH*WW)      // 32768 dataset patches
#define QQ (BB*HH*WW)        // 4096 queries
#define KD 27                // raw feature dim
#define KCH 6                // 6 k16 chunks (96 split dims)

#define NQB 16               // q blocks of 256 rows
#define PSPLIT 18            // 16*18 = 288 blocks = one wave at occ 2
#define NPG (PP/8)           // 4096 patch groups of 8
#define NGR (PP/16)          // 2048 groups of 16 (P-MMA k unit)
#define SGRP 4               // groups per smem stage (8 pg)

// ---------------- device scratch (no allocation allowed) -------------------
__device__ uint4  g_kfrag[NPG * 3 * 32];          // 6 MB  B-fragments (score MMA)
__device__ uint4  g_qfrag[(QQ/16) * KCH * 32];    // 768KB A-fragments (score MMA)
__device__ uint2  g_vfrag[NGR * 32];              // 512KB B-fragments (P-MMA)
__device__ float  g_bias[PP];                     // per-patch logit bias (log2)
__device__ float  g_partial[QQ * PSPLIT * 8];     // m,sw,c0,c1,c2 per (q,split)

// ---------------- helpers ----------------------------------------------
__device__ __forceinline__ float ex2f(float x) {
    float r; asm("ex2.approx.f32 %0,%1;" : "=f"(r) : "f"(x)); return r;
}
__device__ __forceinline__ unsigned pack_bf16x2(float lo, float hi) {
    unsigned r;
    asm("cvt.rn.bf16x2.f32 %0, %1, %2;" : "=r"(r) : "f"(hi), "f"(lo));
    return r;
}
__device__ __forceinline__ uint32_t smem_u32(const void* p) {
    uint32_t a;
    asm("{ .reg .u64 t; cvta.to.shared.u64 t, %1; cvt.u32.u64 %0, t; }"
        : "=r"(a) : "l"(p));
    return a;
}
__device__ __forceinline__ void cp_async16(uint32_t dst, const void* src) {
    asm volatile("cp.async.cg.shared.global [%0], [%1], 16;"
                 :: "r"(dst), "l"(src));
}
#define CP_COMMIT() asm volatile("cp.async.commit_group;" ::: "memory")
#define CP_WAIT1()  asm volatile("cp.async.wait_group 1;" ::: "memory")

__device__ __forceinline__ void split_bf16(float v, unsigned short& h, unsigned short& l) {
    __nv_bfloat16 hb = __float2bfloat16_rn(v);
    float rem = v - __bfloat162float(hb);
    __nv_bfloat16 lb = __float2bfloat16_rn(rem);
    h = __bfloat16_as_ushort(hb);
    l = __bfloat16_as_ushort(lb);
}
#define MMA_BF16(d0,d1,d2,d3,a0,a1,a2,a3,b0,b1) \
    asm volatile("mma.sync.aligned.m16n8k16.row.col.f32.bf16.bf16.f32 " \
                 "{%0,%1,%2,%3}, {%4,%5,%6,%7}, {%8,%9}, {%0,%1,%2,%3};" \
                 : "+f"(d0), "+f"(d1), "+f"(d2), "+f"(d3) \
                 : "r"(a0), "r"(a1), "r"(a2), "r"(a3), "r"(b0), "r"(b1))

// ---------------------------------------------------------------------------
// Prep: score-MMA fragments (Q/K split-bf16), P-MMA V fragments, biases.
// ---------------------------------------------------------------------------
__global__ void prep_kernel(const float* __restrict__ x,
                            const float* __restrict__ images,
                            const float* __restrict__ mu_sched,
                            const float* __restrict__ sigma_sched,
                            const int* __restrict__ tptr)
{
    const int t = *tptr;
    const float mu = mu_sched[t];
    const float sg = sigma_sched[t];
    const float LOG2E = 1.4426950408889634f;
    const float inv2s2 = 1.0f / (2.0f * sg * sg);
    const float a  = 2.0f * mu * inv2s2 * LOG2E;
    const float nb = -mu * mu * inv2s2 * LOG2E;

    int gid = blockIdx.x * blockDim.x + threadIdx.x;

    if (gid < PP) {
        // ---- dataset patch: K fragments + bias ----
        float f[KD];
        unsigned short hb[KD], lb[KD];
        unsigned short v[96];
        int p = gid;
        int n = p >> 10, i = (p >> 5) & 31, j = p & 31;
        float pn = 0.0f;
        #pragma unroll
        for (int c = 0; c < CC; c++)
            #pragma unroll
            for (int di = 0; di < 3; di++)
                #pragma unroll
                for (int dj = 0; dj < 3; dj++) {
                    int ii = i + di - 1, jj = j + dj - 1;
                    float vv = 0.0f;
                    if (ii >= 0 && ii < HH && jj >= 0 && jj < WW)
                        vv = images[(((n*CC + c) << 5) + ii) * WW + jj];
                    f[c*9 + di*3 + dj] = vv;
                    pn += vv * vv;
                }
        #pragma unroll
        for (int k = 0; k < KD; k++) split_bf16(f[k], hb[k], lb[k]);
        #pragma unroll
        for (int k = 0; k < 96; k++)
            v[k] = (k < 27) ? hb[k] : (k < 54) ? lb[k-27] : (k < 81) ? hb[k-54] : 0;

        int pg = p >> 3, nn = p & 7;
        #pragma unroll
        for (int cp = 0; cp < 3; cp++) {
            int c0 = 2*cp*16, c1 = (2*cp+1)*16;
            #pragma unroll
            for (int tt = 0; tt < 4; tt++) {
                uint4 val;
                val.x = (unsigned)v[c0 + 2*tt]     | ((unsigned)v[c0 + 2*tt + 1] << 16);
                val.y = (unsigned)v[c0 + 2*tt + 8] | ((unsigned)v[c0 + 2*tt + 9] << 16);
                val.z = (unsigned)v[c1 + 2*tt]     | ((unsigned)v[c1 + 2*tt + 1] << 16);
                val.w = (unsigned)v[c1 + 2*tt + 8] | ((unsigned)v[c1 + 2*tt + 9] << 16);
                g_kfrag[((pg*3 + cp) << 5) + nn*4 + tt] = val;
            }
        }
        g_bias[p] = nb * pn;
    } else if (gid < PP + QQ) {
        // ---- query: A fragments ----
        float f[KD];
        unsigned short hb[KD], lb[KD];
        unsigned short v[96];
        int q = gid - PP;
        int b = q >> 10, h = (q >> 5) & 31, w0 = q & 31;
        #pragma unroll
        for (int c = 0; c < CC; c++)
            #pragma unroll
            for (int di = 0; di < 3; di++)
                #pragma unroll
                for (int dj = 0; dj < 3; dj++) {
                    int ii = (h + di - 1) & 31, jj = (w0 + dj - 1) & 31;
                    f[c*9 + di*3 + dj] = a * x[(((b*CC + c) << 5) + ii) * WW + jj];
                }
        #pragma unroll
        for (int k = 0; k < KD; k++) split_bf16(f[k], hb[k], lb[k]);
        #pragma unroll
        for (int k = 0; k < 96; k++)
            v[k] = (k < 27) ? hb[k] : (k < 54) ? hb[k-27] : (k < 81) ? lb[k-54] : 0;

        int tile = q >> 4, r = q & 15, rg = r & 7, rh = r >> 3;
        unsigned* qf = (unsigned*)g_qfrag;
        #pragma unroll
        for (int c = 0; c < KCH; c++) {
            #pragma unroll
            for (int tt = 0; tt < 4; tt++) {
                unsigned lo = (unsigned)v[c*16 + 2*tt]     | ((unsigned)v[c*16 + 2*tt + 1] << 16);
                unsigned hi = (unsigned)v[c*16 + 2*tt + 8] | ((unsigned)v[c*16 + 2*tt + 9] << 16);
                unsigned base4 = (((tile*KCH + c) << 5) + rg*4 + tt) << 2;
                qf[base4 + rh]     = lo;
                qf[base4 + 2 + rh] = hi;
            }
        }
    } else if (gid < PP + QQ + NGR*32) {
        // ---- V fragments for P-MMA: cols = c0h,c1h,c2h,1, c0l,c1l,c2l,0 ----
        int idx  = gid - (PP + QQ);
        int gr   = idx >> 5;
        int lane = idx & 31;
        int g    = lane >> 2;      // column index 0..7
        int t4   = lane & 3;       // k pair selector
        float vals[4];             // patches 2t, 2t+1, 2t+8, 2t+9
        #pragma unroll
        for (int e = 0; e < 4; e++) {
            int k = (e < 2) ? (2*t4 + e) : (2*t4 + 8 + (e - 2));
            int p = gr*16 + k;
            float val;
            if (g == 3) val = 1.0f;
            else if (g == 7) val = 0.0f;
            else {
                int c = (g < 3) ? g : (g - 4);
                int n = p >> 10, i = (p >> 5) & 31, j = p & 31;
                float pix = images[((n*CC + c) << 10) + (i << 5) + j];
                __nv_bfloat16 hb = __float2bfloat16_rn(pix);
                val = (g < 3) ? __bfloat162float(hb)
                              : (pix - __bfloat162float(hb));
            }
            vals[e] = val;
        }
        uint2 out;
        out.x = pack_bf16x2(vals[0], vals[1]);
        out.y = pack_bf16x2(vals[2], vals[3]);
        g_vfrag[(gr << 5) + lane] = out;
    }
}

// ---------------------------------------------------------------------------
// Main: mma.sync flash-attention with P-MMA accumulation.
// Grid 16 q-blocks x 18 splits, 256 thr, warp = 32 q-rows (2 row-sets).
// ---------------------------------------------------------------------------
struct Stage {
    uint4 k[8*96];      // 12288 B : 8 pg of score B-fragments
    uint2 v[SGRP*32];   //  1024 B : 4 groups of P-MMA V-fragments
    float bias[64];     //   256 B : biases for 64 patches
};

__global__ void __launch_bounds__(256, 2)
score_main_kernel()
{
    __shared__ __align__(16) Stage stg[2];

    const int bid  = blockIdx.x;
    const int qb   = bid & 15;
    const int sp   = bid >> 4;          // 0..17
    const int tid  = threadIdx.x;
    const int w    = tid >> 5;
    const int lane = tid & 31;
    const int g    = lane >> 2;
    const int t4   = lane & 3;

    // A fragments: 2 row-sets of 16 q-rows each
    uint4 af[2][KCH];
    #pragma unroll
    for (int rs = 0; rs < 2; rs++) {
        int tile = qb*16 + w*2 + rs;
        #pragma unroll
        for (int c = 0; c < KCH; c++)
            af[rs][c] = g_qfrag[((tile*KCH + c) << 5) + lane];
    }

    // state: per rs, per row (g / g+8): max + 2 O-accum regs
    float m_[2][2];
    float o_[2][4];   // o0=O[g][2t], o1=O[g][2t+1], o2=O[g+8][2t], o3=O[g+8][2t+1]
    #pragma unroll
    for (int rs = 0; rs < 2; rs++) {
        m_[rs][0] = -1e30f; m_[rs][1] = -1e30f;
        o_[rs][0] = 0.f; o_[rs][1] = 0.f; o_[rs][2] = 0.f; o_[rs][3] = 0.f;
    }

    // group (16-patch) range for this split
    const int Gg0 = (NGR * sp) / PSPLIT;
    const int Gg1 = (NGR * (sp + 1)) / PSPLIT;
    const int nstages = (Gg1 - Gg0 + SGRP - 1) / SGRP;

    uint32_t kaddr[2], vaddr[2], baddr[2];
    #pragma unroll
    for (int s = 0; s < 2; s++) {
        kaddr[s] = smem_u32(&stg[s].k[0]);
        vaddr[s] = smem_u32(&stg[s].v[0]);
        baddr[s] = smem_u32(&stg[s].bias[0]);
    }

    // prefetch a stage into buffer `dst`
    auto prefetch = [&](int st, int dst) {
        int gr0 = Gg0 + st * SGRP;
        if (gr0 >= Gg1) return;
        int cnt = (Gg1 - gr0 < SGRP) ? (Gg1 - gr0) : SGRP;
        const uint4* ks = g_kfrag + (size_t)(2*gr0) * 96;
        for (int i = tid; i < cnt*192; i += 256)
            cp_async16(kaddr[dst] + i*16, ks + i);
        const uint4* vs = (const uint4*)(g_vfrag + (gr0 << 5));
        for (int i = tid; i < cnt*16; i += 256)
            cp_async16(vaddr[dst] + i*16, vs + i);
        const uint4* bs = (const uint4*)(g_bias + gr0*16);
        for (int i = tid; i < cnt*4; i += 256)
            cp_async16(baddr[dst] + i*16, bs + i);
    };

    prefetch(0, 0);
    CP_COMMIT();

    for (int st = 0; st < nstages; st++) {
        const int cur = st & 1;
        prefetch(st + 1, cur ^ 1);
        CP_COMMIT();
        CP_WAIT1();
        __syncthreads();

        const int gr0 = Gg0 + st * SGRP;
        const int cnt = (Gg1 - gr0 < SGRP) ? (Gg1 - gr0) : SGRP;
        const uint4*  kb = stg[cur].k;
        const uint2*  vb = stg[cur].v;
        const float*  bb = stg[cur].bias;

        for (int gi = 0; gi < cnt; gi++) {
            uint4 e0 = kb[(2*gi)*96      + lane];
            uint4 e1 = kb[(2*gi)*96 + 32 + lane];
            uint4 e2 = kb[(2*gi)*96 + 64 + lane];
            uint4 q0 = kb[(2*gi+1)*96      + lane];
            uint4 q1 = kb[(2*gi+1)*96 + 32 + lane];
            uint4 q2 = kb[(2*gi+1)*96 + 64 + lane];
            float2 bE = *(const float2*)(bb + gi*16 + 2*t4);
            float2 bO = *(const float2*)(bb + gi*16 + 8 + 2*t4);
            uint2  vf = vb[gi*32 + lane];

            #pragma unroll
            for (int rs = 0; rs < 2; rs++) {
                // even-pg chain
                float de0 = bE.x, de1 = bE.y, de2 = bE.x, de3 = bE.y;
                // odd-pg chain (independent)
                float do0 = bO.x, do1 = bO.y, do2 = bO.x, do3 = bO.y;
                MMA_BF16(de0,de1,de2,de3, af[rs][0].x,af[rs][0].y,af[rs][0].z,af[rs][0].w, e0.x,e0.y);
                MMA_BF16(do0,do1,do2,do3, af[rs][0].x,af[rs][0].y,af[rs][0].z,af[rs][0].w, q0.x,q0.y);
                MMA_BF16(de0,de1,de2,de3, af[rs][1].x,af[rs][1].y,af[rs][1].z,af[rs][1].w, e0.z,e0.w);
                MMA_BF16(do0,do1,do2,do3, af[rs][1].x,af[rs][1].y,af[rs][1].z,af[rs][1].w, q0.z,q0.w);
                MMA_BF16(de0,de1,de2,de3, af[rs][2].x,af[rs][2].y,af[rs][2].z,af[rs][2].w, e1.x,e1.y);
                MMA_BF16(do0,do1,do2,do3, af[rs][2].x,af[rs][2].y,af[rs][2].z,af[rs][2].w, q1.x,q1.y);
                MMA_BF16(de0,de1,de2,de3, af[rs][3].x,af[rs][3].y,af[rs][3].z,af[rs][3].w, e1.z,e1.w);
                MMA_BF16(do0,do1,do2,do3, af[rs][3].x,af[rs][3].y,af[rs][3].z,af[rs][3].w, q1.z,q1.w);
                MMA_BF16(de0,de1,de2,de3, af[rs][4].x,af[rs][4].y,af[rs][4].z,af[rs][4].w, e2.x,e2.y);
                MMA_BF16(do0,do1,do2,do3, af[rs][4].x,af[rs][4].y,af[rs][4].z,af[rs][4].w, q2.x,q2.y);
                MMA_BF16(de0,de1,de2,de3, af[rs][5].x,af[rs][5].y,af[rs][5].z,af[rs][5].w, e2.z,e2.w);
                MMA_BF16(do0,do1,do2,do3, af[rs][5].x,af[rs][5].y,af[rs][5].z,af[rs][5].w, q2.z,q2.w);

                // row g: shared max over the 4 column lanes
                {
                    float mx = fmaxf(fmaxf(de0, de1), fmaxf(do0, do1));
                    mx = fmaxf(mx, __shfl_xor_sync(0xffffffffu, mx, 1, 4));
                    mx = fmaxf(mx, __shfl_xor_sync(0xffffffffu, mx, 2, 4));
                    if (mx > m_[rs][0]) {
                        float cr = ex2f(m_[rs][0] - mx);
                        o_[rs][0] *= cr; o_[rs][1] *= cr;
                        m_[rs][0] = mx;
                    }
                }
                // row g+8
                {
                    float mx = fmaxf(fmaxf(de2, de3), fmaxf(do2, do3));
                    mx = fmaxf(mx, __shfl_xor_sync(0xffffffffu, mx, 1, 4));
                    mx = fmaxf(mx, __shfl_xor_sync(0xffffffffu, mx, 2, 4));
                    if (mx > m_[rs][1]) {
                        float cr = ex2f(m_[rs][1] - mx);
                        o_[rs][2] *= cr; o_[rs][3] *= cr;
                        m_[rs][1] = mx;
                    }
                }

                // weights + P-MMA (A = P fragment, B = V fragment)
                unsigned a0 = pack_bf16x2(ex2f(de0 - m_[rs][0]), ex2f(de1 - m_[rs][0]));
                unsigned a1 = pack_bf16x2(ex2f(de2 - m_[rs][1]), ex2f(de3 - m_[rs][1]));
                unsigned a2 = pack_bf16x2(ex2f(do0 - m_[rs][0]), ex2f(do1 - m_[rs][0]));
                unsigned a3 = pack_bf16x2(ex2f(do2 - m_[rs][1]), ex2f(do3 - m_[rs][1]));
                MMA_BF16(o_[rs][0], o_[rs][1], o_[rs][2], o_[rs][3],
                         a0, a1, a2, a3, vf.x, vf.y);
            }
        }
        __syncthreads();
    }

    // epilogue: combine hi/lo columns and gather per-row state
    #pragma unroll
    for (int rs = 0; rs < 2; rs++) {
        // row g: lane t holds cols 2t,2t+1 in o0,o1
        float p0 = o_[rs][0] + __shfl_xor_sync(0xffffffffu, o_[rs][0], 2, 4);
        float p1 = o_[rs][1] + __shfl_xor_sync(0xffffffffu, o_[rs][1], 2, 4);
        // t0: p0=c0, p1=c1 ; t1: p0=c2, p1=sw
        float c2v = __shfl_sync(0xffffffffu, p0, 1, 4);
        float swv = __shfl_sync(0xffffffffu, p1, 1, 4);
        // row g+8
        float r0 = o_[rs][2] + __shfl_xor_sync(0xffffffffu, o_[rs][2], 2, 4);
        float r1 = o_[rs][3] + __shfl_xor_sync(0xffffffffu, o_[rs][3], 2, 4);
        float c2v2 = __shfl_sync(0xffffffffu, r0, 1, 4);
        float swv2 = __shfl_sync(0xffffffffu, r1, 1, 4);

        if (t4 == 0) {
            int tile = qb*16 + w*2 + rs;
            int q0r = tile*16 + g;
            float* o = g_partial + ((size_t)q0r * PSPLIT + sp) * 8;
            o[0] = m_[rs][0]; o[1] = swv; o[2] = p0; o[3] = p1; o[4] = c2v;
            float* o2 = g_partial + ((size_t)(q0r + 8) * PSPLIT + sp) * 8;
            o2[0] = m_[rs][1]; o2[1] = swv2; o2[2] = r0; o2[3] = r1; o2[4] = c2v2;
        }
    }
}

// ---------------------------------------------------------------------------
// Finalize: merge PSPLIT partials per query (log2 domain), form output.
// ---------------------------------------------------------------------------
__global__ void finalize_kernel(const float* __restrict__ x,
                                const float* __restrict__ mu_sched,
                                const float* __restrict__ sigma_sched,
                                const int* __restrict__ tptr,
                                float* __restrict__ out)
{
    int q = blockIdx.x * blockDim.x + threadIdx.x;
    if (q >= QQ) return;

    const int t = *tptr;
    const float mu = mu_sched[t];
    const float sg = sigma_sched[t];
    const float is2 = 1.0f / (sg * sg);

    const float* pr = g_partial + (size_t)q * PSPLIT * 8;

    float M = -1e30f;
    #pragma unroll
    for (int i = 0; i < PSPLIT; i++) M = fmaxf(M, pr[i*8]);

    float S = 0.f, c0 = 0.f, c1 = 0.f, c2 = 0.f;
    #pragma unroll
    for (int i = 0; i < PSPLIT; i++) {
        float cr = ex2f(pr[i*8] - M);
        S  += pr[i*8 + 1] * cr;
        c0 += pr[i*8 + 2] * cr;
        c1 += pr[i*8 + 3] * cr;
        c2 += pr[i*8 + 4] * cr;
    }
    float inv = 1.0f / S;

    int b = q >> 10;
    int pix = q & 1023;

    out[((b*CC + 0) << 10) + pix] = -(x[((b*CC + 0) << 10) + pix] - mu * c0 * inv) * is2;
    out[((b*CC + 1) << 10) + pix] = -(x[((b*CC + 1) << 10) + pix] - mu * c1 * inv) * is2;
    out[((b*CC + 2) << 10) + pix] = -(x[((b*CC + 2) << 10) + pix] - mu * c2 * inv) * is2;
}

// ---------------------------------------------------------------------------
extern "C" void kernel_launch(void* const* d_in, const int* in_sizes, int n_in,
                              void* d_out, int out_size)
{
    const float* x      = (const float*)d_in[0];
    const float* images = (const float*)d_in[1];
    const float* mu_s   = (const float*)d_in[2];
    const float* sg_s   = (const float*)d_in[3];
    const int*   tptr   = (const int*)d_in[4];
    float* out = (float*)d_out;

    int nthreads = PP + QQ + NGR*32;
    prep_kernel<<<(nthreads + 255) / 256, 256>>>(x, images, mu_s, sg_s, tptr);
    score_main_kernel<<<NQB * PSPLIT, 256>>>();
    finalize_kernel<<<(QQ + 255) / 256, 256>>>(x, mu_s, sg_s, tptr, out);
}

// round 11
// speedup vs baseline: 1.4739x; 1.0212x over previous
#include <cuda_runtime.h>
#include <cuda_bf16.h>
#include <math.h>
#include <cstdint>

// ---------------- problem constants ----------------
#define BB 4
#define CC 3
#define HH 32
#define WW 32
#define NIMG 32
#define PP (NIMG*HH*WW)      // 32768 dataset patches
#define QQ (BB*HH*WW)        // 4096 queries
#define KD 27                // raw feature dim
#define KCH 6                // 6 k16 chunks (96 split dims)

#define NQB 16               // q blocks of 256 rows
#define PSPLIT 18            // 16*18 = 288 blocks = one wave at occ 2
#define NPG (PP/8)           // 4096 patch groups of 8
#define NGR (PP/16)          // 2048 groups of 16 (P-MMA k unit)
#define SGRP 4               // groups per smem stage (8 pg)

// ---------------- device scratch (no allocation allowed) -------------------
__device__ uint4  g_kfrag[NPG * 3 * 32];          // 6 MB  B-fragments (score MMA)
__device__ uint4  g_qfrag[(QQ/16) * KCH * 32];    // 768KB A-fragments (score MMA)
__device__ uint2  g_vfrag[NGR * 32];              // 512KB B-fragments (P-MMA)
__device__ float  g_bias[PP];                     // per-patch logit bias (log2)
__device__ float  g_partial[QQ * PSPLIT * 8];     // m,sw,c0,c1,c2 per (q,split)

// ---------------- helpers ----------------------------------------------
__device__ __forceinline__ float ex2f(float x) {
    float r; asm("ex2.approx.f32 %0,%1;" : "=f"(r) : "f"(x)); return r;
}
__device__ __forceinline__ unsigned pack_bf16x2(float lo, float hi) {
    unsigned r;
    asm("cvt.rn.bf16x2.f32 %0, %1, %2;" : "=r"(r) : "f"(hi), "f"(lo));
    return r;
}
__device__ __forceinline__ uint32_t smem_u32(const void* p) {
    uint32_t a;
    asm("{ .reg .u64 t; cvta.to.shared.u64 t, %1; cvt.u32.u64 %0, t; }"
        : "=r"(a) : "l"(p));
    return a;
}
__device__ __forceinline__ void cp_async16(uint32_t dst, const void* src) {
    asm volatile("cp.async.cg.shared.global [%0], [%1], 16;"
                 :: "r"(dst), "l"(src));
}
#define CP_COMMIT() asm volatile("cp.async.commit_group;" ::: "memory")
#define CP_WAIT1()  asm volatile("cp.async.wait_group 1;" ::: "memory")

__device__ __forceinline__ void split_bf16(float v, unsigned short& h, unsigned short& l) {
    __nv_bfloat16 hb = __float2bfloat16_rn(v);
    float rem = v - __bfloat162float(hb);
    __nv_bfloat16 lb = __float2bfloat16_rn(rem);
    h = __bfloat16_as_ushort(hb);
    l = __bfloat16_as_ushort(lb);
}
#define MMA_BF16(d0,d1,d2,d3,a0,a1,a2,a3,b0,b1) \
    asm volatile("mma.sync.aligned.m16n8k16.row.col.f32.bf16.bf16.f32 " \
                 "{%0,%1,%2,%3}, {%4,%5,%6,%7}, {%8,%9}, {%0,%1,%2,%3};" \
                 : "+f"(d0), "+f"(d1), "+f"(d2), "+f"(d3) \
                 : "r"(a0), "r"(a1), "r"(a2), "r"(a3), "r"(b0), "r"(b1))

// ---------------------------------------------------------------------------
// Prep: score-MMA fragments (Q/K split-bf16), P-MMA V fragments, biases.
// ---------------------------------------------------------------------------
__global__ void prep_kernel(const float* __restrict__ x,
                            const float* __restrict__ images,
                            const float* __restrict__ mu_sched,
                            const float* __restrict__ sigma_sched,
                            const int* __restrict__ tptr)
{
    const int t = *tptr;
    const float mu = mu_sched[t];
    const float sg = sigma_sched[t];
    const float LOG2E = 1.4426950408889634f;
    const float inv2s2 = 1.0f / (2.0f * sg * sg);
    const float a  = 2.0f * mu * inv2s2 * LOG2E;
    const float nb = -mu * mu * inv2s2 * LOG2E;

    int gid = blockIdx.x * blockDim.x + threadIdx.x;

    if (gid < PP) {
        // ---- dataset patch: K fragments + bias ----
        float f[KD];
        unsigned short hb[KD], lb[KD];
        unsigned short v[96];
        int p = gid;
        int n = p >> 10, i = (p >> 5) & 31, j = p & 31;
        float pn = 0.0f;
        #pragma unroll
        for (int c = 0; c < CC; c++)
            #pragma unroll
            for (int di = 0; di < 3; di++)
                #pragma unroll
                for (int dj = 0; dj < 3; dj++) {
                    int ii = i + di - 1, jj = j + dj - 1;
                    float vv = 0.0f;
                    if (ii >= 0 && ii < HH && jj >= 0 && jj < WW)
                        vv = images[(((n*CC + c) << 5) + ii) * WW + jj];
                    f[c*9 + di*3 + dj] = vv;
                    pn += vv * vv;
                }
        #pragma unroll
        for (int k = 0; k < KD; k++) split_bf16(f[k], hb[k], lb[k]);
        #pragma unroll
        for (int k = 0; k < 96; k++)
            v[k] = (k < 27) ? hb[k] : (k < 54) ? lb[k-27] : (k < 81) ? hb[k-54] : 0;

        int pg = p >> 3, nn = p & 7;
        #pragma unroll
        for (int cp = 0; cp < 3; cp++) {
            int c0 = 2*cp*16, c1 = (2*cp+1)*16;
            #pragma unroll
            for (int tt = 0; tt < 4; tt++) {
                uint4 val;
                val.x = (unsigned)v[c0 + 2*tt]     | ((unsigned)v[c0 + 2*tt + 1] << 16);
                val.y = (unsigned)v[c0 + 2*tt + 8] | ((unsigned)v[c0 + 2*tt + 9] << 16);
                val.z = (unsigned)v[c1 + 2*tt]     | ((unsigned)v[c1 + 2*tt + 1] << 16);
                val.w = (unsigned)v[c1 + 2*tt + 8] | ((unsigned)v[c1 + 2*tt + 9] << 16);
                g_kfrag[((pg*3 + cp) << 5) + nn*4 + tt] = val;
            }
        }
        g_bias[p] = nb * pn;
    } else if (gid < PP + QQ) {
        // ---- query: A fragments ----
        float f[KD];
        unsigned short hb[KD], lb[KD];
        unsigned short v[96];
        int q = gid - PP;
        int b = q >> 10, h = (q >> 5) & 31, w0 = q & 31;
        #pragma unroll
        for (int c = 0; c < CC; c++)
            #pragma unroll
            for (int di = 0; di < 3; di++)
                #pragma unroll
                for (int dj = 0; dj < 3; dj++) {
                    int ii = (h + di - 1) & 31, jj = (w0 + dj - 1) & 31;
                    f[c*9 + di*3 + dj] = a * x[(((b*CC + c) << 5) + ii) * WW + jj];
                }
        #pragma unroll
        for (int k = 0; k < KD; k++) split_bf16(f[k], hb[k], lb[k]);
        #pragma unroll
        for (int k = 0; k < 96; k++)
            v[k] = (k < 27) ? hb[k] : (k < 54) ? hb[k-27] : (k < 81) ? lb[k-54] : 0;

        int tile = q >> 4, r = q & 15, rg = r & 7, rh = r >> 3;
        unsigned* qf = (unsigned*)g_qfrag;
        #pragma unroll
        for (int c = 0; c < KCH; c++) {
            #pragma unroll
            for (int tt = 0; tt < 4; tt++) {
                unsigned lo = (unsigned)v[c*16 + 2*tt]     | ((unsigned)v[c*16 + 2*tt + 1] << 16);
                unsigned hi = (unsigned)v[c*16 + 2*tt + 8] | ((unsigned)v[c*16 + 2*tt + 9] << 16);
                unsigned base4 = (((tile*KCH + c) << 5) + rg*4 + tt) << 2;
                qf[base4 + rh]     = lo;
                qf[base4 + 2 + rh] = hi;
            }
        }
    } else if (gid < PP + QQ + NGR*32) {
        // ---- V fragments for P-MMA: cols = c0h,c1h,c2h,1, c0l,c1l,c2l,0 ----
        int idx  = gid - (PP + QQ);
        int gr   = idx >> 5;
        int lane = idx & 31;
        int g    = lane >> 2;      // column index 0..7
        int t4   = lane & 3;       // k pair selector
        float vals[4];             // patches 2t, 2t+1, 2t+8, 2t+9
        #pragma unroll
        for (int e = 0; e < 4; e++) {
            int k = (e < 2) ? (2*t4 + e) : (2*t4 + 8 + (e - 2));
            int p = gr*16 + k;
            float val;
            if (g == 3) val = 1.0f;
            else if (g == 7) val = 0.0f;
            else {
                int c = (g < 3) ? g : (g - 4);
                int n = p >> 10, i = (p >> 5) & 31, j = p & 31;
                float pix = images[((n*CC + c) << 10) + (i << 5) + j];
                __nv_bfloat16 hb = __float2bfloat16_rn(pix);
                val = (g < 3) ? __bfloat162float(hb)
                              : (pix - __bfloat162float(hb));
            }
            vals[e] = val;
        }
        uint2 out;
        out.x = pack_bf16x2(vals[0], vals[1]);
        out.y = pack_bf16x2(vals[2], vals[3]);
        g_vfrag[(gr << 5) + lane] = out;
    }
}

// ---------------------------------------------------------------------------
// Main: mma.sync flash-attention with P-MMA accumulation.
// Two-phase inner loop: 24 back-to-back score MMAs, then branchless epilogue.
// ---------------------------------------------------------------------------
struct Stage {
    uint4 k[8*96];      // 12288 B : 8 pg of score B-fragments
    uint2 v[SGRP*32];   //  1024 B : 4 groups of P-MMA V-fragments
    float bias[64];     //   256 B : biases for 64 patches
};

__global__ void __launch_bounds__(256, 2)
score_main_kernel()
{
    __shared__ __align__(16) Stage stg[2];

    const int bid  = blockIdx.x;
    const int qb   = bid & 15;
    const int sp   = bid >> 4;          // 0..17
    const int tid  = threadIdx.x;
    const int w    = tid >> 5;
    const int lane = tid & 31;
    const int t4   = lane & 3;
    const int g    = lane >> 2;

    // A fragments: 2 row-sets of 16 q-rows each
    uint4 af[2][KCH];
    #pragma unroll
    for (int rs = 0; rs < 2; rs++) {
        int tile = qb*16 + w*2 + rs;
        #pragma unroll
        for (int c = 0; c < KCH; c++)
            af[rs][c] = g_qfrag[((tile*KCH + c) << 5) + lane];
    }

    float m_[2][2];
    float o_[2][4];
    #pragma unroll
    for (int rs = 0; rs < 2; rs++) {
        m_[rs][0] = -1e30f; m_[rs][1] = -1e30f;
        o_[rs][0] = 0.f; o_[rs][1] = 0.f; o_[rs][2] = 0.f; o_[rs][3] = 0.f;
    }

    const int Gg0 = (NGR * sp) / PSPLIT;
    const int Gg1 = (NGR * (sp + 1)) / PSPLIT;
    const int nstages = (Gg1 - Gg0 + SGRP - 1) / SGRP;

    uint32_t kaddr[2], vaddr[2], baddr[2];
    #pragma unroll
    for (int s = 0; s < 2; s++) {
        kaddr[s] = smem_u32(&stg[s].k[0]);
        vaddr[s] = smem_u32(&stg[s].v[0]);
        baddr[s] = smem_u32(&stg[s].bias[0]);
    }

    auto prefetch = [&](int st, int dst) {
        int gr0 = Gg0 + st * SGRP;
        if (gr0 >= Gg1) return;
        int cnt = (Gg1 - gr0 < SGRP) ? (Gg1 - gr0) : SGRP;
        const uint4* ks = g_kfrag + (size_t)(2*gr0) * 96;
        for (int i = tid; i < cnt*192; i += 256)
            cp_async16(kaddr[dst] + i*16, ks + i);
        const uint4* vs = (const uint4*)(g_vfrag + (gr0 << 5));
        for (int i = tid; i < cnt*16; i += 256)
            cp_async16(vaddr[dst] + i*16, vs + i);
        const uint4* bs = (const uint4*)(g_bias + gr0*16);
        for (int i = tid; i < cnt*4; i += 256)
            cp_async16(baddr[dst] + i*16, bs + i);
    };

    prefetch(0, 0);
    CP_COMMIT();

    for (int st = 0; st < nstages; st++) {
        const int cur = st & 1;
        prefetch(st + 1, cur ^ 1);
        CP_COMMIT();
        CP_WAIT1();
        __syncthreads();

        const int gr0 = Gg0 + st * SGRP;
        const int cnt = (Gg1 - gr0 < SGRP) ? (Gg1 - gr0) : SGRP;
        const uint4*  kb = stg[cur].k;
        const uint2*  vb = stg[cur].v;
        const float*  bb = stg[cur].bias;

        for (int gi = 0; gi < cnt; gi++) {
            uint4 e0 = kb[(2*gi)*96      + lane];
            uint4 e1 = kb[(2*gi)*96 + 32 + lane];
            uint4 e2 = kb[(2*gi)*96 + 64 + lane];
            uint4 q0 = kb[(2*gi+1)*96      + lane];
            uint4 q1 = kb[(2*gi+1)*96 + 32 + lane];
            uint4 q2 = kb[(2*gi+1)*96 + 64 + lane];
            float2 bE = *(const float2*)(bb + gi*16 + 2*t4);
            float2 bO = *(const float2*)(bb + gi*16 + 8 + 2*t4);
            uint2  vf = vb[gi*32 + lane];

            // ---------------- phase 1: 24 score MMAs, 4 independent chains
            float sE[2][4], sO[2][4];
            #pragma unroll
            for (int rs = 0; rs < 2; rs++) {
                sE[rs][0] = bE.x; sE[rs][1] = bE.y; sE[rs][2] = bE.x; sE[rs][3] = bE.y;
                sO[rs][0] = bO.x; sO[rs][1] = bO.y; sO[rs][2] = bO.x; sO[rs][3] = bO.y;
            }
            #pragma unroll
            for (int rs = 0; rs < 2; rs++) {
                MMA_BF16(sE[rs][0],sE[rs][1],sE[rs][2],sE[rs][3],
                         af[rs][0].x,af[rs][0].y,af[rs][0].z,af[rs][0].w, e0.x,e0.y);
                MMA_BF16(sO[rs][0],sO[rs][1],sO[rs][2],sO[rs][3],
                         af[rs][0].x,af[rs][0].y,af[rs][0].z,af[rs][0].w, q0.x,q0.y);
                MMA_BF16(sE[rs][0],sE[rs][1],sE[rs][2],sE[rs][3],
                         af[rs][1].x,af[rs][1].y,af[rs][1].z,af[rs][1].w, e0.z,e0.w);
                MMA_BF16(sO[rs][0],sO[rs][1],sO[rs][2],sO[rs][3],
                         af[rs][1].x,af[rs][1].y,af[rs][1].z,af[rs][1].w, q0.z,q0.w);
                MMA_BF16(sE[rs][0],sE[rs][1],sE[rs][2],sE[rs][3],
                         af[rs][2].x,af[rs][2].y,af[rs][2].z,af[rs][2].w, e1.x,e1.y);
                MMA_BF16(sO[rs][0],sO[rs][1],sO[rs][2],sO[rs][3],
                         af[rs][2].x,af[rs][2].y,af[rs][2].z,af[rs][2].w, q1.x,q1.y);
                MMA_BF16(sE[rs][0],sE[rs][1],sE[rs][2],sE[rs][3],
                         af[rs][3].x,af[rs][3].y,af[rs][3].z,af[rs][3].w, e1.z,e1.w);
                MMA_BF16(sO[rs][0],sO[rs][1],sO[rs][2],sO[rs][3],
                         af[rs][3].x,af[rs][3].y,af[rs][3].z,af[rs][3].w, q1.z,q1.w);
                MMA_BF16(sE[rs][0],sE[rs][1],sE[rs][2],sE[rs][3],
                         af[rs][4].x,af[rs][4].y,af[rs][4].z,af[rs][4].w, e2.x,e2.y);
                MMA_BF16(sO[rs][0],sO[rs][1],sO[rs][2],sO[rs][3],
                         af[rs][4].x,af[rs][4].y,af[rs][4].z,af[rs][4].w, q2.x,q2.y);
                MMA_BF16(sE[rs][0],sE[rs][1],sE[rs][2],sE[rs][3],
                         af[rs][5].x,af[rs][5].y,af[rs][5].z,af[rs][5].w, e2.z,e2.w);
                MMA_BF16(sO[rs][0],sO[rs][1],sO[rs][2],sO[rs][3],
                         af[rs][5].x,af[rs][5].y,af[rs][5].z,af[rs][5].w, q2.z,q2.w);
            }

            // ---------------- phase 2: branchless online softmax + P-MMA
            #pragma unroll
            for (int rs = 0; rs < 2; rs++) {
                // row g
                float mx0 = fmaxf(fmaxf(sE[rs][0], sE[rs][1]), fmaxf(sO[rs][0], sO[rs][1]));
                mx0 = fmaxf(mx0, __shfl_xor_sync(0xffffffffu, mx0, 1, 4));
                mx0 = fmaxf(mx0, __shfl_xor_sync(0xffffffffu, mx0, 2, 4));
                float mn0 = fmaxf(m_[rs][0], mx0);
                float cr0 = ex2f(m_[rs][0] - mn0);      // == 1.0 when no update
                o_[rs][0] *= cr0; o_[rs][1] *= cr0;
                m_[rs][0] = mn0;
                // row g+8
                float mx1 = fmaxf(fmaxf(sE[rs][2], sE[rs][3]), fmaxf(sO[rs][2], sO[rs][3]));
                mx1 = fmaxf(mx1, __shfl_xor_sync(0xffffffffu, mx1, 1, 4));
                mx1 = fmaxf(mx1, __shfl_xor_sync(0xffffffffu, mx1, 2, 4));
                float mn1 = fmaxf(m_[rs][1], mx1);
                float cr1 = ex2f(m_[rs][1] - mn1);
                o_[rs][2] *= cr1; o_[rs][3] *= cr1;
                m_[rs][1] = mn1;

                unsigned a0 = pack_bf16x2(ex2f(sE[rs][0] - mn0), ex2f(sE[rs][1] - mn0));
                unsigned a1 = pack_bf16x2(ex2f(sE[rs][2] - mn1), ex2f(sE[rs][3] - mn1));
                unsigned a2 = pack_bf16x2(ex2f(sO[rs][0] - mn0), ex2f(sO[rs][1] - mn0));
                unsigned a3 = pack_bf16x2(ex2f(sO[rs][2] - mn1), ex2f(sO[rs][3] - mn1));
                MMA_BF16(o_[rs][0], o_[rs][1], o_[rs][2], o_[rs][3],
                         a0, a1, a2, a3, vf.x, vf.y);
            }
        }
        __syncthreads();
    }

    // epilogue: combine hi/lo columns and gather per-row state
    #pragma unroll
    for (int rs = 0; rs < 2; rs++) {
        float p0 = o_[rs][0] + __shfl_xor_sync(0xffffffffu, o_[rs][0], 2, 4);
        float p1 = o_[rs][1] + __shfl_xor_sync(0xffffffffu, o_[rs][1], 2, 4);
        float c2v = __shfl_sync(0xffffffffu, p0, 1, 4);
        float swv = __shfl_sync(0xffffffffu, p1, 1, 4);
        float r0 = o_[rs][2] + __shfl_xor_sync(0xffffffffu, o_[rs][2], 2, 4);
        float r1 = o_[rs][3] + __shfl_xor_sync(0xffffffffu, o_[rs][3], 2, 4);
        float c2v2 = __shfl_sync(0xffffffffu, r0, 1, 4);
        float swv2 = __shfl_sync(0xffffffffu, r1, 1, 4);

        if (t4 == 0) {
            int tile = qb*16 + w*2 + rs;
            int q0r = tile*16 + g;
            float* o = g_partial + ((size_t)q0r * PSPLIT + sp) * 8;
            o[0] = m_[rs][0]; o[1] = swv; o[2] = p0; o[3] = p1; o[4] = c2v;
            float* o2 = g_partial + ((size_t)(q0r + 8) * PSPLIT + sp) * 8;
            o2[0] = m_[rs][1]; o2[1] = swv2; o2[2] = r0; o2[3] = r1; o2[4] = c2v2;
        }
    }
}

// ---------------------------------------------------------------------------
// Finalize: merge PSPLIT partials per query (log2 domain), form output.
// ---------------------------------------------------------------------------
__global__ void finalize_kernel(const float* __restrict__ x,
                                const float* __restrict__ mu_sched,
                                const float* __restrict__ sigma_sched,
                                const int* __restrict__ tptr,
                                float* __restrict__ out)
{
    int q = blockIdx.x * blockDim.x + threadIdx.x;
    if (q >= QQ) return;

    const int t = *tptr;
    const float mu = mu_sched[t];
    const float sg = sigma_sched[t];
    const float is2 = 1.0f / (sg * sg);

    const float* pr = g_partial + (size_t)q * PSPLIT * 8;

    float M = -1e30f;
    #pragma unroll
    for (int i = 0; i < PSPLIT; i++) M = fmaxf(M, pr[i*8]);

    float S = 0.f, c0 = 0.f, c1 = 0.f, c2 = 0.f;
    #pragma unroll
    for (int i = 0; i < PSPLIT; i++) {
        float cr = ex2f(pr[i*8] - M);
        S  += pr[i*8 + 1] * cr;
        c0 += pr[i*8 + 2] * cr;
        c1 += pr[i*8 + 3] * cr;
        c2 += pr[i*8 + 4] * cr;
    }
    float inv = 1.0f / S;

    int b = q >> 10;
    int pix = q & 1023;

    out[((b*CC + 0) << 10) + pix] = -(x[((b*CC + 0) << 10) + pix] - mu * c0 * inv) * is2;
    out[((b*CC + 1) << 10) + pix] = -(x[((b*CC + 1) << 10) + pix] - mu * c1 * inv) * is2;
    out[((b*CC + 2) << 10) + pix] = -(x[((b*CC + 2) << 10) + pix] - mu * c2 * inv) * is2;
}

// ---------------------------------------------------------------------------
extern "C" void kernel_launch(void* const* d_in, const int* in_sizes, int n_in,
                              void* d_out, int out_size)
{
    const float* x      = (const float*)d_in[0];
    const float* images = (const float*)d_in[1];
    const float* mu_s   = (const float*)d_in[2];
    const float* sg_s   = (const float*)d_in[3];
    const int*   tptr   = (const int*)d_in[4];
    float* out = (float*)d_out;

    int nthreads = PP + QQ + NGR*32;
    prep_kernel<<<(nthreads + 255) / 256, 256>>>(x, images, mu_s, sg_s, tptr);
    score_main_kernel<<<NQB * PSPLIT, 256>>>();
    finalize_kernel<<<(QQ + 255) / 256, 256>>>(x, mu_s, sg_s, tptr, out);
}

// round 12
// speedup vs baseline: 1.5879x; 1.0773x over previous
#include <cuda_runtime.h>
#include <cuda_bf16.h>
#include <math.h>
#include <cstdint>

// ---------------- problem constants ----------------
#define BB 4
#define CC 3
#define HH 32
#define WW 32
#define NIMG 32
#define PP (NIMG*HH*WW)      // 32768 dataset patches
#define QQ (BB*HH*WW)        // 4096 queries
#define KD 27                // raw feature dim
#define KCH 5                // 5 k16 chunks (80 split dims: qh27|qh27|ql26)

#define NQB 16               // q blocks of 256 rows
#define PSPLIT 18            // 16*18 = 288 blocks = one wave at occ 2
#define NPG (PP/8)           // 4096 patch groups of 8
#define NGR (PP/16)          // 2048 groups of 16 (P-MMA k unit)
#define SGRP 4               // groups per smem stage (8 pg)

// ---------------- device scratch (no allocation allowed) -------------------
__device__ uint4  g_kfrag4[NPG * 2 * 32];         // 4 MB  chunks 0..3 B-fragments
__device__ uint4  g_kfrag2[NPG * 16];             // 1 MB  chunk 4 B-fragments (2 lanes/uint4)
__device__ uint4  g_qfrag[(QQ/16) * KCH * 32];    // 640KB A-fragments
__device__ uint2  g_vfrag[NGR * 32];              // 512KB B-fragments (P-MMA)
__device__ float  g_bias[PP];                     // per-patch logit bias (log2)
__device__ float  g_partial[QQ * PSPLIT * 8];     // m,sw,c0,c1,c2 per (q,split)

// ---------------- helpers ----------------------------------------------
__device__ __forceinline__ float ex2f(float x) {
    float r; asm("ex2.approx.f32 %0,%1;" : "=f"(r) : "f"(x)); return r;
}
__device__ __forceinline__ unsigned pack_bf16x2(float lo, float hi) {
    unsigned r;
    asm("cvt.rn.bf16x2.f32 %0, %1, %2;" : "=r"(r) : "f"(hi), "f"(lo));
    return r;
}
__device__ __forceinline__ uint32_t smem_u32(const void* p) {
    uint32_t a;
    asm("{ .reg .u64 t; cvta.to.shared.u64 t, %1; cvt.u32.u64 %0, t; }"
        : "=r"(a) : "l"(p));
    return a;
}
__device__ __forceinline__ void cp_async16(uint32_t dst, const void* src) {
    asm volatile("cp.async.cg.shared.global [%0], [%1], 16;"
                 :: "r"(dst), "l"(src));
}
#define CP_COMMIT() asm volatile("cp.async.commit_group;" ::: "memory")
#define CP_WAIT1()  asm volatile("cp.async.wait_group 1;" ::: "memory")

__device__ __forceinline__ void split_bf16(float v, unsigned short& h, unsigned short& l) {
    __nv_bfloat16 hb = __float2bfloat16_rn(v);
    float rem = v - __bfloat162float(hb);
    __nv_bfloat16 lb = __float2bfloat16_rn(rem);
    h = __bfloat16_as_ushort(hb);
    l = __bfloat16_as_ushort(lb);
}
#define MMA_BF16(d0,d1,d2,d3,a0,a1,a2,a3,b0,b1) \
    asm volatile("mma.sync.aligned.m16n8k16.row.col.f32.bf16.bf16.f32 " \
                 "{%0,%1,%2,%3}, {%4,%5,%6,%7}, {%8,%9}, {%0,%1,%2,%3};" \
                 : "+f"(d0), "+f"(d1), "+f"(d2), "+f"(d3) \
                 : "r"(a0), "r"(a1), "r"(a2), "r"(a3), "r"(b0), "r"(b1))

// ---------------------------------------------------------------------------
// Prep: score-MMA fragments (Q/K split-bf16, 80 dims), P-MMA V fragments, bias.
// A row: [qh(27) | qh(27) | ql(26)] ; B row: [kh(27) | kl(27) | kh(26)]
// ---------------------------------------------------------------------------
__global__ void prep_kernel(const float* __restrict__ x,
                            const float* __restrict__ images,
                            const float* __restrict__ mu_sched,
                            const float* __restrict__ sigma_sched,
                            const int* __restrict__ tptr)
{
    const int t = *tptr;
    const float mu = mu_sched[t];
    const float sg = sigma_sched[t];
    const float LOG2E = 1.4426950408889634f;
    const float inv2s2 = 1.0f / (2.0f * sg * sg);
    const float a  = 2.0f * mu * inv2s2 * LOG2E;
    const float nb = -mu * mu * inv2s2 * LOG2E;

    int gid = blockIdx.x * blockDim.x + threadIdx.x;

    if (gid < PP) {
        // ---- dataset patch: K fragments + bias ----
        float f[KD];
        unsigned short hb[KD], lb[KD];
        unsigned short v[80];
        int p = gid;
        int n = p >> 10, i = (p >> 5) & 31, j = p & 31;
        float pn = 0.0f;
        #pragma unroll
        for (int c = 0; c < CC; c++)
            #pragma unroll
            for (int di = 0; di < 3; di++)
                #pragma unroll
                for (int dj = 0; dj < 3; dj++) {
                    int ii = i + di - 1, jj = j + dj - 1;
                    float vv = 0.0f;
                    if (ii >= 0 && ii < HH && jj >= 0 && jj < WW)
                        vv = images[(((n*CC + c) << 5) + ii) * WW + jj];
                    f[c*9 + di*3 + dj] = vv;
                    pn += vv * vv;
                }
        #pragma unroll
        for (int k = 0; k < KD; k++) split_bf16(f[k], hb[k], lb[k]);
        #pragma unroll
        for (int k = 0; k < 80; k++)
            v[k] = (k < 27) ? hb[k] : (k < 54) ? lb[k-27] : hb[k-54];

        int pg = p >> 3, nn = p & 7;
        #pragma unroll
        for (int cp = 0; cp < 2; cp++) {
            int c0 = 32*cp, c1 = 32*cp + 16;
            #pragma unroll
            for (int tt = 0; tt < 4; tt++) {
                uint4 val;
                val.x = (unsigned)v[c0 + 2*tt]     | ((unsigned)v[c0 + 2*tt + 1] << 16);
                val.y = (unsigned)v[c0 + 2*tt + 8] | ((unsigned)v[c0 + 2*tt + 9] << 16);
                val.z = (unsigned)v[c1 + 2*tt]     | ((unsigned)v[c1 + 2*tt + 1] << 16);
                val.w = (unsigned)v[c1 + 2*tt + 8] | ((unsigned)v[c1 + 2*tt + 9] << 16);
                g_kfrag4[((pg*2 + cp) << 5) + nn*4 + tt] = val;
            }
        }
        // chunk 4 -> uint2 per lane, packed two lanes per uint4
        unsigned* k2 = (unsigned*)g_kfrag2;
        #pragma unroll
        for (int tt = 0; tt < 4; tt++) {
            unsigned b0 = (unsigned)v[64 + 2*tt]     | ((unsigned)v[64 + 2*tt + 1] << 16);
            unsigned b1 = (unsigned)v[64 + 2*tt + 8] | ((unsigned)v[64 + 2*tt + 9] << 16);
            int lane = nn*4 + tt;
            k2[(pg << 6) + lane*2]     = b0;
            k2[(pg << 6) + lane*2 + 1] = b1;
        }
        g_bias[p] = nb * pn;
    } else if (gid < PP + QQ) {
        // ---- query: A fragments ----
        float f[KD];
        unsigned short hb[KD], lb[KD];
        unsigned short v[80];
        int q = gid - PP;
        int b = q >> 10, h = (q >> 5) & 31, w0 = q & 31;
        #pragma unroll
        for (int c = 0; c < CC; c++)
            #pragma unroll
            for (int di = 0; di < 3; di++)
                #pragma unroll
                for (int dj = 0; dj < 3; dj++) {
                    int ii = (h + di - 1) & 31, jj = (w0 + dj - 1) & 31;
                    f[c*9 + di*3 + dj] = a * x[(((b*CC + c) << 5) + ii) * WW + jj];
                }
        #pragma unroll
        for (int k = 0; k < KD; k++) split_bf16(f[k], hb[k], lb[k]);
        #pragma unroll
        for (int k = 0; k < 80; k++)
            v[k] = (k < 27) ? hb[k] : (k < 54) ? hb[k-27] : lb[k-54];

        int tile = q >> 4, r = q & 15, rg = r & 7, rh = r >> 3;
        unsigned* qf = (unsigned*)g_qfrag;
        #pragma unroll
        for (int c = 0; c < KCH; c++) {
            #pragma unroll
            for (int tt = 0; tt < 4; tt++) {
                unsigned lo = (unsigned)v[c*16 + 2*tt]     | ((unsigned)v[c*16 + 2*tt + 1] << 16);
                unsigned hi = (unsigned)v[c*16 + 2*tt + 8] | ((unsigned)v[c*16 + 2*tt + 9] << 16);
                unsigned base4 = (((tile*KCH + c) << 5) + rg*4 + tt) << 2;
                qf[base4 + rh]     = lo;
                qf[base4 + 2 + rh] = hi;
            }
        }
    } else if (gid < PP + QQ + NGR*32) {
        // ---- V fragments for P-MMA: cols = c0h,c1h,c2h,1, c0l,c1l,c2l,0 ----
        int idx  = gid - (PP + QQ);
        int gr   = idx >> 5;
        int lane = idx & 31;
        int g    = lane >> 2;
        int t4   = lane & 3;
        float vals[4];
        #pragma unroll
        for (int e = 0; e < 4; e++) {
            int k = (e < 2) ? (2*t4 + e) : (2*t4 + 8 + (e - 2));
            int p = gr*16 + k;
            float val;
            if (g == 3) val = 1.0f;
            else if (g == 7) val = 0.0f;
            else {
                int c = (g < 3) ? g : (g - 4);
                int n = p >> 10, i = (p >> 5) & 31, j = p & 31;
                float pix = images[((n*CC + c) << 10) + (i << 5) + j];
                __nv_bfloat16 hb = __float2bfloat16_rn(pix);
                val = (g < 3) ? __bfloat162float(hb)
                              : (pix - __bfloat162float(hb));
            }
            vals[e] = val;
        }
        uint2 out;
        out.x = pack_bf16x2(vals[0], vals[1]);
        out.y = pack_bf16x2(vals[2], vals[3]);
        g_vfrag[(gr << 5) + lane] = out;
    }
}

// ---------------------------------------------------------------------------
// Main: mma.sync flash-attention, 80-dim split, P-MMA accumulation.
// ---------------------------------------------------------------------------
struct Stage {
    uint4 k4[8*64];     // 8192 B : 8 pg, chunks 0..3
    uint2 k2[8*32];     // 2048 B : 8 pg, chunk 4
    uint2 v[SGRP*32];   // 1024 B : P-MMA V-fragments
    float bias[64];     //  256 B
};

__global__ void __launch_bounds__(256, 2)
score_main_kernel()
{
    __shared__ __align__(16) Stage stg[2];

    const int bid  = blockIdx.x;
    const int qb   = bid & 15;
    const int sp   = bid >> 4;          // 0..17
    const int tid  = threadIdx.x;
    const int w    = tid >> 5;
    const int lane = tid & 31;
    const int t4   = lane & 3;
    const int g    = lane >> 2;

    // A fragments: 2 row-sets of 16 q-rows each, 5 chunks
    uint4 af[2][KCH];
    #pragma unroll
    for (int rs = 0; rs < 2; rs++) {
        int tile = qb*16 + w*2 + rs;
        #pragma unroll
        for (int c = 0; c < KCH; c++)
            af[rs][c] = g_qfrag[((tile*KCH + c) << 5) + lane];
    }

    float m_[2][2];
    float o_[2][4];
    #pragma unroll
    for (int rs = 0; rs < 2; rs++) {
        m_[rs][0] = -1e30f; m_[rs][1] = -1e30f;
        o_[rs][0] = 0.f; o_[rs][1] = 0.f; o_[rs][2] = 0.f; o_[rs][3] = 0.f;
    }

    const int Gg0 = (NGR * sp) / PSPLIT;
    const int Gg1 = (NGR * (sp + 1)) / PSPLIT;
    const int nstages = (Gg1 - Gg0 + SGRP - 1) / SGRP;

    uint32_t k4a[2], k2a[2], va[2], ba[2];
    #pragma unroll
    for (int s = 0; s < 2; s++) {
        k4a[s] = smem_u32(&stg[s].k4[0]);
        k2a[s] = smem_u32(&stg[s].k2[0]);
        va[s]  = smem_u32(&stg[s].v[0]);
        ba[s]  = smem_u32(&stg[s].bias[0]);
    }

    auto prefetch = [&](int st, int dst) {
        int gr0 = Gg0 + st * SGRP;
        if (gr0 >= Gg1) return;
        int cnt = (Gg1 - gr0 < SGRP) ? (Gg1 - gr0) : SGRP;
        const uint4* ks = g_kfrag4 + (size_t)(2*gr0) * 64;
        for (int i = tid; i < cnt*128; i += 256)
            cp_async16(k4a[dst] + i*16, ks + i);
        const uint4* k2s = g_kfrag2 + (size_t)(2*gr0) * 16;
        for (int i = tid; i < cnt*32; i += 256)
            cp_async16(k2a[dst] + i*16, k2s + i);
        const uint4* vs = (const uint4*)(g_vfrag + (gr0 << 5));
        for (int i = tid; i < cnt*16; i += 256)
            cp_async16(va[dst] + i*16, vs + i);
        const uint4* bs = (const uint4*)(g_bias + gr0*16);
        for (int i = tid; i < cnt*4; i += 256)
            cp_async16(ba[dst] + i*16, bs + i);
    };

    prefetch(0, 0);
    CP_COMMIT();

    for (int st = 0; st < nstages; st++) {
        const int cur = st & 1;
        prefetch(st + 1, cur ^ 1);
        CP_COMMIT();
        CP_WAIT1();
        __syncthreads();

        const int gr0 = Gg0 + st * SGRP;
        const int cnt = (Gg1 - gr0 < SGRP) ? (Gg1 - gr0) : SGRP;
        const uint4*  kb4 = stg[cur].k4;
        const uint2*  kb2 = stg[cur].k2;
        const uint2*  vb  = stg[cur].v;
        const float*  bb  = stg[cur].bias;

        for (int gi = 0; gi < cnt; gi++) {
            uint4 e0 = kb4[(2*gi)*64      + lane];
            uint4 e1 = kb4[(2*gi)*64 + 32 + lane];
            uint2 e2 = kb2[(2*gi)*32      + lane];
            uint4 q0 = kb4[(2*gi+1)*64      + lane];
            uint4 q1 = kb4[(2*gi+1)*64 + 32 + lane];
            uint2 q2 = kb2[(2*gi+1)*32      + lane];
            float2 bE = *(const float2*)(bb + gi*16 + 2*t4);
            float2 bO = *(const float2*)(bb + gi*16 + 8 + 2*t4);
            uint2  vf = vb[gi*32 + lane];

            // ---------------- phase 1: 20 score MMAs, 4 interleaved chains
            float sE[2][4], sO[2][4];
            #pragma unroll
            for (int rs = 0; rs < 2; rs++) {
                sE[rs][0] = bE.x; sE[rs][1] = bE.y; sE[rs][2] = bE.x; sE[rs][3] = bE.y;
                sO[rs][0] = bO.x; sO[rs][1] = bO.y; sO[rs][2] = bO.x; sO[rs][3] = bO.y;
            }
            #pragma unroll
            for (int c = 0; c < KCH; c++) {
                unsigned be0, be1, bo0, bo1;
                if      (c == 0) { be0 = e0.x; be1 = e0.y; bo0 = q0.x; bo1 = q0.y; }
                else if (c == 1) { be0 = e0.z; be1 = e0.w; bo0 = q0.z; bo1 = q0.w; }
                else if (c == 2) { be0 = e1.x; be1 = e1.y; bo0 = q1.x; bo1 = q1.y; }
                else if (c == 3) { be0 = e1.z; be1 = e1.w; bo0 = q1.z; bo1 = q1.w; }
                else             { be0 = e2.x; be1 = e2.y; bo0 = q2.x; bo1 = q2.y; }
                MMA_BF16(sE[0][0],sE[0][1],sE[0][2],sE[0][3],
                         af[0][c].x,af[0][c].y,af[0][c].z,af[0][c].w, be0,be1);
                MMA_BF16(sO[0][0],sO[0][1],sO[0][2],sO[0][3],
                         af[0][c].x,af[0][c].y,af[0][c].z,af[0][c].w, bo0,bo1);
                MMA_BF16(sE[1][0],sE[1][1],sE[1][2],sE[1][3],
                         af[1][c].x,af[1][c].y,af[1][c].z,af[1][c].w, be0,be1);
                MMA_BF16(sO[1][0],sO[1][1],sO[1][2],sO[1][3],
                         af[1][c].x,af[1][c].y,af[1][c].z,af[1][c].w, bo0,bo1);
            }

            // ---------------- phase 2: branchless online softmax + P-MMA
            #pragma unroll
            for (int rs = 0; rs < 2; rs++) {
                float mx0 = fmaxf(fmaxf(sE[rs][0], sE[rs][1]), fmaxf(sO[rs][0], sO[rs][1]));
                mx0 = fmaxf(mx0, __shfl_xor_sync(0xffffffffu, mx0, 1, 4));
                mx0 = fmaxf(mx0, __shfl_xor_sync(0xffffffffu, mx0, 2, 4));
                float mn0 = fmaxf(m_[rs][0], mx0);
                float cr0 = ex2f(m_[rs][0] - mn0);
                o_[rs][0] *= cr0; o_[rs][1] *= cr0;
                m_[rs][0] = mn0;

                float mx1 = fmaxf(fmaxf(sE[rs][2], sE[rs][3]), fmaxf(sO[rs][2], sO[rs][3]));
                mx1 = fmaxf(mx1, __shfl_xor_sync(0xffffffffu, mx1, 1, 4));
                mx1 = fmaxf(mx1, __shfl_xor_sync(0xffffffffu, mx1, 2, 4));
                float mn1 = fmaxf(m_[rs][1], mx1);
                float cr1 = ex2f(m_[rs][1] - mn1);
                o_[rs][2] *= cr1; o_[rs][3] *= cr1;
                m_[rs][1] = mn1;

                unsigned a0 = pack_bf16x2(ex2f(sE[rs][0] - mn0), ex2f(sE[rs][1] - mn0));
                unsigned a1 = pack_bf16x2(ex2f(sE[rs][2] - mn1), ex2f(sE[rs][3] - mn1));
                unsigned a2 = pack_bf16x2(ex2f(sO[rs][0] - mn0), ex2f(sO[rs][1] - mn0));
                unsigned a3 = pack_bf16x2(ex2f(sO[rs][2] - mn1), ex2f(sO[rs][3] - mn1));
                MMA_BF16(o_[rs][0], o_[rs][1], o_[rs][2], o_[rs][3],
                         a0, a1, a2, a3, vf.x, vf.y);
            }
        }
        __syncthreads();
    }

    // epilogue: combine hi/lo columns and gather per-row state
    #pragma unroll
    for (int rs = 0; rs < 2; rs++) {
        float p0 = o_[rs][0] + __shfl_xor_sync(0xffffffffu, o_[rs][0], 2, 4);
        float p1 = o_[rs][1] + __shfl_xor_sync(0xffffffffu, o_[rs][1], 2, 4);
        float c2v = __shfl_sync(0xffffffffu, p0, 1, 4);
        float swv = __shfl_sync(0xffffffffu, p1, 1, 4);
        float r0 = o_[rs][2] + __shfl_xor_sync(0xffffffffu, o_[rs][2], 2, 4);
        float r1 = o_[rs][3] + __shfl_xor_sync(0xffffffffu, o_[rs][3], 2, 4);
        float c2v2 = __shfl_sync(0xffffffffu, r0, 1, 4);
        float swv2 = __shfl_sync(0xffffffffu, r1, 1, 4);

        if (t4 == 0) {
            int tile = qb*16 + w*2 + rs;
            int q0r = tile*16 + g;
            float* o = g_partial + ((size_t)q0r * PSPLIT + sp) * 8;
            o[0] = m_[rs][0]; o[1] = swv; o[2] = p0; o[3] = p1; o[4] = c2v;
            float* o2 = g_partial + ((size_t)(q0r + 8) * PSPLIT + sp) * 8;
            o2[0] = m_[rs][1]; o2[1] = swv2; o2[2] = r0; o2[3] = r1; o2[4] = c2v2;
        }
    }
}

// ---------------------------------------------------------------------------
// Finalize: merge PSPLIT partials per query (log2 domain), form output.
// ---------------------------------------------------------------------------
__global__ void finalize_kernel(const float* __restrict__ x,
                                const float* __restrict__ mu_sched,
                                const float* __restrict__ sigma_sched,
                                const int* __restrict__ tptr,
                                float* __restrict__ out)
{
    int q = blockIdx.x * blockDim.x + threadIdx.x;
    if (q >= QQ) return;

    const int t = *tptr;
    const float mu = mu_sched[t];
    const float sg = sigma_sched[t];
    const float is2 = 1.0f / (sg * sg);

    const float* pr = g_partial + (size_t)q * PSPLIT * 8;

    float M = -1e30f;
    #pragma unroll
    for (int i = 0; i < PSPLIT; i++) M = fmaxf(M, pr[i*8]);

    float S = 0.f, c0 = 0.f, c1 = 0.f, c2 = 0.f;
    #pragma unroll
    for (int i = 0; i < PSPLIT; i++) {
        float cr = ex2f(pr[i*8] - M);
        S  += pr[i*8 + 1] * cr;
        c0 += pr[i*8 + 2] * cr;
        c1 += pr[i*8 + 3] * cr;
        c2 += pr[i*8 + 4] * cr;
    }
    float inv = 1.0f / S;

    int b = q >> 10;
    int pix = q & 1023;

    out[((b*CC + 0) << 10) + pix] = -(x[((b*CC + 0) << 10) + pix] - mu * c0 * inv) * is2;
    out[((b*CC + 1) << 10) + pix] = -(x[((b*CC + 1) << 10) + pix] - mu * c1 * inv) * is2;
    out[((b*CC + 2) << 10) + pix] = -(x[((b*CC + 2) << 10) + pix] - mu * c2 * inv) * is2;
}

// ---------------------------------------------------------------------------
extern "C" void kernel_launch(void* const* d_in, const int* in_sizes, int n_in,
                              void* d_out, int out_size)
{
    const float* x      = (const float*)d_in[0];
    const float* images = (const float*)d_in[1];
    const float* mu_s   = (const float*)d_in[2];
    const float* sg_s   = (const float*)d_in[3];
    const int*   tptr   = (const int*)d_in[4];
    float* out = (float*)d_out;

    int nthreads = PP + QQ + NGR*32;
    prep_kernel<<<(nthreads + 255) / 256, 256>>>(x, images, mu_s, sg_s, tptr);
    score_main_kernel<<<NQB * PSPLIT, 256>>>();
    finalize_kernel<<<(QQ + 255) / 256, 256>>>(x, mu_s, sg_s, tptr, out);
}